// round 1
// baseline (speedup 1.0000x reference)
#include <cuda_runtime.h>
#include <cuda_bf16.h>
#include <math.h>

// ---------------- problem constants ----------------
#define Bb 4
#define Ll 2048
#define Dd 2048
#define NHh 16
#define DHh 128
#define DHRr 64
#define DCc 1024
#define Mtok (Bb*Ll)            // 8192
#define QKD 192                 // DH + DHR

// ---------------- device scratch (static, allocation-free) ----------------
__device__ float g_ckv [(size_t)Mtok*DCc];        // 8192x1024
__device__ float g_cq  [(size_t)Mtok*DCc];        // 8192x1024
__device__ float g_kr  [(size_t)Mtok*DHRr];       // 8192x64
__device__ float g_kc  [(size_t)Mtok*Dd];         // 8192x2048
__device__ float g_vfl [(size_t)Mtok*Dd];         // 8192x2048
__device__ float g_qc  [(size_t)Mtok*Dd];         // 8192x2048
__device__ float g_qr  [(size_t)Mtok*(NHh*DHRr)]; // 8192x1024
__device__ float g_q   [(size_t)Bb*NHh*Ll*QKD];   // (64, 2048, 192)
__device__ float g_k   [(size_t)Bb*NHh*Ll*QKD];
__device__ float g_v   [(size_t)Bb*NHh*Ll*DHh];   // (64, 2048, 128)
__device__ float g_ao  [(size_t)Mtok*Dd];         // attention out, (B*L, 2048)

// ---------------- generic tiled SGEMM (row-major, C = A*B) ----------------
template<int BM, int BN, int BK, int TM, int TN>
__global__ void __launch_bounds__((BM/TM)*(BN/TN))
sgemm_kernel(const float* __restrict__ A, const float* __restrict__ B,
             float* __restrict__ C, int M, int N, int K)
{
    constexpr int THREADS = (BM/TM)*(BN/TN);
    __shared__ float As[BK][BM];
    __shared__ float Bs[BK][BN];
    const int tid = threadIdx.x;
    const int tx  = tid % (BN/TN);
    const int ty  = tid / (BN/TN);
    const float* Ab = A + (size_t)blockIdx.y * BM * K;
    const float* Bt = B + (size_t)blockIdx.x * BN;

    float acc[TM][TN];
#pragma unroll
    for (int i=0;i<TM;i++)
#pragma unroll
        for (int j=0;j<TN;j++) acc[i][j]=0.f;

    for (int k0 = 0; k0 < K; k0 += BK) {
#pragma unroll
        for (int i = tid; i < BM*BK; i += THREADS) {
            int r = i / BK, c = i % BK;
            As[c][r] = Ab[(size_t)r*K + k0 + c];
        }
#pragma unroll
        for (int i = tid; i < BK*BN; i += THREADS) {
            int r = i / BN, c = i % BN;
            Bs[r][c] = Bt[(size_t)(k0+r)*N + c];
        }
        __syncthreads();
#pragma unroll
        for (int kk=0; kk<BK; kk++) {
            float ar[TM], br[TN];
#pragma unroll
            for (int i=0;i<TM;i+=4) {
                float4 v = *(const float4*)&As[kk][ty*TM+i];
                ar[i]=v.x; ar[i+1]=v.y; ar[i+2]=v.z; ar[i+3]=v.w;
            }
#pragma unroll
            for (int j=0;j<TN;j+=4) {
                float4 v = *(const float4*)&Bs[kk][tx*TN+j];
                br[j]=v.x; br[j+1]=v.y; br[j+2]=v.z; br[j+3]=v.w;
            }
#pragma unroll
            for (int i=0;i<TM;i++)
#pragma unroll
                for (int j=0;j<TN;j++)
                    acc[i][j] += ar[i]*br[j];
        }
        __syncthreads();
    }
    float* Cb = C + (size_t)blockIdx.y*BM*N + (size_t)blockIdx.x*BN;
#pragma unroll
    for (int i=0;i<TM;i++)
#pragma unroll
        for (int j=0;j<TN;j+=4) {
            float4 v = make_float4(acc[i][j],acc[i][j+1],acc[i][j+2],acc[i][j+3]);
            *(float4*)&Cb[(size_t)(ty*TM+i)*N + tx*TN + j] = v;
        }
}

// ---------------- prep: RoPE + concat + normalize + scale + reshape ----------------
__global__ void __launch_bounds__(256) prep_kernel(const float* __restrict__ s_qk_ptr)
{
    const int bl = blockIdx.x;          // 0..8191  (= b*L + l)
    const int b  = bl >> 11;            // L = 2048
    const int l  = bl & 2047;
    const int t  = threadIdx.x;         // 256 threads

    __shared__ float cs[32], sn[32];
    __shared__ float krr[64];
    __shared__ float red[256];

    const float s_qk = *s_qk_ptr;

    if (t < 32) {
        float inv = powf(10000.0f, -2.0f * (float)t / 64.0f);
        float ang = (float)l * inv;
        cs[t] = cosf(ang);
        sn[t] = sinf(ang);
    }
    __syncthreads();

    // rope the (head-shared) k_rope vector
    if (t < 64) {
        int j = t & 31;
        float v   = g_kr[(size_t)bl*64 + t];
        float rot = (t < 32) ? -g_kr[(size_t)bl*64 + t + 32]
                             :  g_kr[(size_t)bl*64 + t - 32];
        krr[t] = v*cs[j] + rot*sn[j];
    }
    __syncthreads();

    for (int h = 0; h < NHh; h++) {
        const size_t off192 = ((size_t)(b*NHh + h)*Ll + l) * QKD;
        const size_t off128 = ((size_t)(b*NHh + h)*Ll + l) * DHh;

        // ---- K: concat(k_c[128], roped k_rope[64]) ----
        float kv = 0.f;
        if (t < 128)      kv = g_kc[(size_t)bl*Dd + h*DHh + t];
        else if (t < 192) kv = krr[t-128];
        red[t] = kv*kv;
        __syncthreads();
        for (int s=128; s>0; s>>=1) { if (t<s) red[t]+=red[t+s]; __syncthreads(); }
        {
            float invn = 1.0f / fmaxf(sqrtf(red[0]), 1e-12f);
            if (t < 192) g_k[off192 + t] = kv * invn;
        }
        __syncthreads();

        // ---- Q: concat(q_c[128], roped q_rope[64]) ----
        float qv = 0.f;
        if (t < 128) qv = g_qc[(size_t)bl*Dd + h*DHh + t];
        else if (t < 192) {
            int j  = t - 128;
            int jj = j & 31;
            const float* qrp = g_qr + (size_t)bl*(NHh*DHRr) + h*DHRr;
            float v   = qrp[j];
            float rot = (j < 32) ? -qrp[j+32] : qrp[j-32];
            qv = v*cs[jj] + rot*sn[jj];
        }
        red[t] = qv*qv;
        __syncthreads();
        for (int s=128; s>0; s>>=1) { if (t<s) red[t]+=red[t+s]; __syncthreads(); }
        {
            float invq = s_qk / fmaxf(sqrtf(red[0]), 1e-12f);
            if (t < 192) g_q[off192 + t] = qv * invq;
        }
        // ---- V: reshape to head-contiguous ----
        if (t < 128) g_v[off128 + t] = g_vfl[(size_t)bl*Dd + h*DHh + t];
        __syncthreads();
    }
}

// ---------------- flash attention (fp32, causal, BQ=BK=64) ----------------
// grid: (L/64, B*NH); 256 threads (16x16); S micro 4x4; O micro 4x8
__global__ void __launch_bounds__(256) attn_kernel()
{
    extern __shared__ float sm[];
    float* Qs = sm;                   // [192][64] (transposed: dim-major)
    float* Ks = Qs + QKD*64;          // [192][64]
    float* Vs = Ks + QKD*64;          // [64][128]
    float* Ps = Vs + 64*128;          // [64][64]

    const int qt = (gridDim.x - 1) - blockIdx.x;   // heavy blocks first
    const int bh = blockIdx.y;
    const int q0 = qt * 64;
    const float* Qg = g_q + (size_t)bh*Ll*QKD;
    const float* Kg = g_k + (size_t)bh*Ll*QKD;
    const float* Vg = g_v + (size_t)bh*Ll*DHh;

    const int tid = threadIdx.x;
    const int tx = tid & 15;      // S col group / O col group
    const int ty = tid >> 4;      // row group

    for (int i = tid; i < 64*QKD; i += 256) {
        int r = i / QKD, d = i % QKD;
        Qs[d*64 + r] = Qg[(size_t)(q0 + r)*QKD + d];
    }

    float O[4][8];
    float m_i[4], l_i[4];
#pragma unroll
    for (int i=0;i<4;i++){
        m_i[i] = -1e30f; l_i[i] = 0.f;
#pragma unroll
        for (int j=0;j<8;j++) O[i][j]=0.f;
    }

    for (int kt = 0; kt <= qt; kt++) {
        const int k0 = kt * 64;
        for (int i = tid; i < 64*QKD; i += 256) {
            int r = i / QKD, d = i % QKD;
            Ks[d*64 + r] = Kg[(size_t)(k0 + r)*QKD + d];
        }
        for (int i = tid; i < 64*DHh; i += 256)
            Vs[i] = Vg[(size_t)k0*DHh + i];
        __syncthreads();

        // S = Q K^T  (4x4 per thread)
        float S[4][4];
#pragma unroll
        for (int i=0;i<4;i++)
#pragma unroll
            for (int j=0;j<4;j++) S[i][j]=0.f;

        for (int k = 0; k < QKD; k++) {
            float4 a = *(const float4*)&Qs[k*64 + ty*4];
            float4 b = *(const float4*)&Ks[k*64 + tx*4];
            float ar[4] = {a.x,a.y,a.z,a.w};
            float br[4] = {b.x,b.y,b.z,b.w};
#pragma unroll
            for (int i=0;i<4;i++)
#pragma unroll
                for (int j=0;j<4;j++)
                    S[i][j] += ar[i]*br[j];
        }

        if (kt == qt) {
#pragma unroll
            for (int i=0;i<4;i++)
#pragma unroll
                for (int j=0;j<4;j++)
                    if (tx*4+j > ty*4+i) S[i][j] = -1e30f;
        }

        // online softmax (row stats across the 16 tx lanes = half-warp)
#pragma unroll
        for (int i=0;i<4;i++) {
            float mx = fmaxf(fmaxf(S[i][0],S[i][1]), fmaxf(S[i][2],S[i][3]));
#pragma unroll
            for (int o=8;o>0;o>>=1) mx = fmaxf(mx, __shfl_xor_sync(0xffffffffu, mx, o));
            float mnew = fmaxf(m_i[i], mx);
            float corr = __expf(m_i[i] - mnew);
            float rs = 0.f;
#pragma unroll
            for (int j=0;j<4;j++) {
                float p = __expf(S[i][j] - mnew);
                S[i][j] = p; rs += p;
            }
#pragma unroll
            for (int o=8;o>0;o>>=1) rs += __shfl_xor_sync(0xffffffffu, rs, o);
            l_i[i] = l_i[i]*corr + rs;
            m_i[i] = mnew;
#pragma unroll
            for (int j=0;j<8;j++) O[i][j] *= corr;
        }

        // stage P, then O += P @ V
#pragma unroll
        for (int i=0;i<4;i++)
            *(float4*)&Ps[(ty*4+i)*64 + tx*4] = make_float4(S[i][0],S[i][1],S[i][2],S[i][3]);
        __syncthreads();

        for (int k = 0; k < 64; k++) {
            float4 v0 = *(const float4*)&Vs[k*128 + tx*8];
            float4 v1 = *(const float4*)&Vs[k*128 + tx*8 + 4];
#pragma unroll
            for (int i=0;i<4;i++) {
                float p = Ps[(ty*4+i)*64 + k];
                O[i][0]+=p*v0.x; O[i][1]+=p*v0.y; O[i][2]+=p*v0.z; O[i][3]+=p*v0.w;
                O[i][4]+=p*v1.x; O[i][5]+=p*v1.y; O[i][6]+=p*v1.z; O[i][7]+=p*v1.w;
            }
        }
        __syncthreads();
    }

    // epilogue -> (B*L, NH*DH) layout for the output projection
    const int b = bh >> 4, h = bh & 15;
#pragma unroll
    for (int i=0;i<4;i++) {
        float inv = 1.0f / l_i[i];
        int l = q0 + ty*4 + i;
        float* dst = g_ao + ((size_t)(b*Ll + l))*Dd + h*DHh + tx*8;
        float4 o0 = make_float4(O[i][0]*inv,O[i][1]*inv,O[i][2]*inv,O[i][3]*inv);
        float4 o1 = make_float4(O[i][4]*inv,O[i][5]*inv,O[i][6]*inv,O[i][7]*inv);
        *(float4*)&dst[0] = o0;
        *(float4*)&dst[4] = o1;
    }
}

// ---------------- launch ----------------
extern "C" void kernel_launch(void* const* d_in, const int* in_sizes, int n_in,
                              void* d_out, int out_size)
{
    const float* x     = (const float*)d_in[0];
    const float* W_DKV = (const float*)d_in[1];
    const float* W_UK  = (const float*)d_in[2];
    const float* W_UV  = (const float*)d_in[3];
    const float* W_DQ  = (const float*)d_in[4];
    const float* W_UQ  = (const float*)d_in[5];
    const float* W_QR  = (const float*)d_in[6];
    const float* W_KR  = (const float*)d_in[7];
    const float* W_O   = (const float*)d_in[8];
    const float* s_qk  = (const float*)d_in[9];
    float* out = (float*)d_out;

    float *ckv, *cq, *kr, *kc, *vfl, *qc, *qr, *ao;
    cudaGetSymbolAddress((void**)&ckv, g_ckv);
    cudaGetSymbolAddress((void**)&cq,  g_cq);
    cudaGetSymbolAddress((void**)&kr,  g_kr);
    cudaGetSymbolAddress((void**)&kc,  g_kc);
    cudaGetSymbolAddress((void**)&vfl, g_vfl);
    cudaGetSymbolAddress((void**)&qc,  g_qc);
    cudaGetSymbolAddress((void**)&qr,  g_qr);
    cudaGetSymbolAddress((void**)&ao,  g_ao);

    cudaFuncSetAttribute(attn_kernel, cudaFuncAttributeMaxDynamicSharedMemorySize,
                         (QKD*64 + QKD*64 + 64*128 + 64*64) * (int)sizeof(float));

    dim3 thr(256);

    // down / rope projections from x
    sgemm_kernel<128,128,8,8,8><<<dim3(DCc/128, Mtok/128), thr>>>(x, W_DKV, ckv, Mtok, DCc, Dd);
    sgemm_kernel<128,128,8,8,8><<<dim3(DCc/128, Mtok/128), thr>>>(x, W_DQ,  cq,  Mtok, DCc, Dd);
    sgemm_kernel< 64, 64,8,4,4><<<dim3(1,        Mtok/64 ), thr>>>(x, W_KR,  kr,  Mtok, DHRr, Dd);

    // up projections
    sgemm_kernel<128,128,8,8,8><<<dim3(Dd/128, Mtok/128), thr>>>(ckv, W_UK, kc,  Mtok, Dd,  DCc);
    sgemm_kernel<128,128,8,8,8><<<dim3(Dd/128, Mtok/128), thr>>>(ckv, W_UV, vfl, Mtok, Dd,  DCc);
    sgemm_kernel<128,128,8,8,8><<<dim3(Dd/128, Mtok/128), thr>>>(cq,  W_UQ, qc,  Mtok, Dd,  DCc);
    sgemm_kernel<128,128,8,8,8><<<dim3((NHh*DHRr)/128, Mtok/128), thr>>>(cq, W_QR, qr, Mtok, NHh*DHRr, DCc);

    // rope + concat + normalize + reshape
    prep_kernel<<<Mtok, 256>>>(s_qk);

    // causal flash attention
    size_t smem = (size_t)(QKD*64 + QKD*64 + 64*128 + 64*64) * sizeof(float);
    attn_kernel<<<dim3(Ll/64, Bb*NHh), 256, smem>>>();

    // output projection -> d_out
    sgemm_kernel<128,128,8,8,8><<<dim3(Dd/128, Mtok/128), thr>>>(ao, W_O, out, Mtok, Dd, Dd);
}

// round 2
// speedup vs baseline: 1.7985x; 1.7985x over previous
#include <cuda_runtime.h>
#include <cuda_bf16.h>
#include <math.h>

// ---------------- problem constants ----------------
#define Bb 4
#define Ll 2048
#define Dd 2048
#define NHh 16
#define DHh 128
#define DHRr 64
#define DCc 1024
#define Mtok (Bb*Ll)            // 8192
#define QKD 192                 // DH + DHR

// ---------------- device scratch (static, allocation-free) ----------------
__device__ float g_ckv [(size_t)Mtok*DCc];        // 8192x1024
__device__ float g_cq  [(size_t)Mtok*DCc];        // 8192x1024
__device__ float g_kr  [(size_t)Mtok*DHRr];       // 8192x64
__device__ float g_kc  [(size_t)Mtok*Dd];         // 8192x2048
__device__ float g_vfl [(size_t)Mtok*Dd];         // 8192x2048
__device__ float g_qc  [(size_t)Mtok*Dd];         // 8192x2048
__device__ float g_qr  [(size_t)Mtok*(NHh*DHRr)]; // 8192x1024
__device__ float g_q   [(size_t)Bb*NHh*Ll*QKD];   // (64, 2048, 192)
__device__ float g_k   [(size_t)Bb*NHh*Ll*QKD];
__device__ float g_v   [(size_t)Bb*NHh*Ll*DHh];   // (64, 2048, 128)
__device__ float g_ao  [(size_t)Mtok*Dd];         // attention out, (B*L, 2048)

// ---------------- tf32 helpers ----------------
__device__ __forceinline__ unsigned f2tf32(float f) {
    unsigned r;
    asm("cvt.rna.tf32.f32 %0, %1;" : "=r"(r) : "f"(f));
    return r;
}

__device__ __forceinline__ void mma_tf32(float* d, const unsigned* a, const unsigned* b) {
    asm volatile(
        "mma.sync.aligned.m16n8k8.row.col.f32.tf32.tf32.f32 "
        "{%0,%1,%2,%3}, {%4,%5,%6,%7}, {%8,%9}, {%0,%1,%2,%3};"
        : "+f"(d[0]), "+f"(d[1]), "+f"(d[2]), "+f"(d[3])
        : "r"(a[0]), "r"(a[1]), "r"(a[2]), "r"(a[3]), "r"(b[0]), "r"(b[1]));
}

// ---------------- tf32 tensor-core GEMM: C = A(MxK) * B(KxN), row-major ----
// 128x128x32 CTA tile, 8 warps (2x4), 64x32 warp tile, m16n8k8 atoms
#define G_AS 36          // As row stride (floats): bank = 4r+c, conflict-free
#define G_BS 136         // Bs row stride (floats): bank = 8c+r, conflict-free
__global__ void __launch_bounds__(256)
tf32_gemm(const float* __restrict__ A, const float* __restrict__ B,
          float* __restrict__ C, int M, int N, int K)
{
    __shared__ unsigned As[128*G_AS];
    __shared__ unsigned Bs[32*G_BS];

    const int tid  = threadIdx.x;
    const int lane = tid & 31;
    const int warp = tid >> 5;
    const int wm = warp >> 2;        // 0..1
    const int wn = warp & 3;         // 0..3
    const int r = lane >> 2;         // 0..7
    const int c = lane & 3;          // 0..3

    const float* Ag = A + (size_t)blockIdx.y * 128 * K;
    const float* Bg = B + (size_t)blockIdx.x * 128;

    float acc[4][4][4];
#pragma unroll
    for (int i=0;i<4;i++)
#pragma unroll
        for (int j=0;j<4;j++)
#pragma unroll
            for (int t=0;t<4;t++) acc[i][j][t]=0.f;

    float4 pa[4], pb[4];

    // --- first tile load (k0 = 0) ---
#pragma unroll
    for (int i=0;i<4;i++) {
        int f4 = tid + i*256;
        pa[i] = *(const float4*)&Ag[(size_t)(f4>>3)*K + (f4&7)*4];
        pb[i] = *(const float4*)&Bg[(size_t)(f4>>5)*N + (f4&31)*4];
    }
#pragma unroll
    for (int i=0;i<4;i++) {
        int f4 = tid + i*256;
        unsigned* ad = &As[(f4>>3)*G_AS + (f4&7)*4];
        ad[0]=f2tf32(pa[i].x); ad[1]=f2tf32(pa[i].y); ad[2]=f2tf32(pa[i].z); ad[3]=f2tf32(pa[i].w);
        unsigned* bd = &Bs[(f4>>5)*G_BS + (f4&31)*4];
        bd[0]=f2tf32(pb[i].x); bd[1]=f2tf32(pb[i].y); bd[2]=f2tf32(pb[i].z); bd[3]=f2tf32(pb[i].w);
    }
    __syncthreads();

    for (int k0 = 32; ; k0 += 32) {
        const bool more = (k0 < K);
        if (more) {
#pragma unroll
            for (int i=0;i<4;i++) {
                int f4 = tid + i*256;
                pa[i] = *(const float4*)&Ag[(size_t)(f4>>3)*K + k0 + (f4&7)*4];
                pb[i] = *(const float4*)&Bg[(size_t)(k0 + (f4>>5))*N + (f4&31)*4];
            }
        }

        // ---- compute on current smem tile ----
#pragma unroll
        for (int kk=0; kk<32; kk+=8) {
            unsigned af[4][4], bf[4][2];
#pragma unroll
            for (int ma=0;ma<4;ma++) {
                int m = wm*64 + ma*16;
                af[ma][0] = As[(m+r  )*G_AS + kk + c  ];
                af[ma][1] = As[(m+r+8)*G_AS + kk + c  ];
                af[ma][2] = As[(m+r  )*G_AS + kk + c+4];
                af[ma][3] = As[(m+r+8)*G_AS + kk + c+4];
            }
#pragma unroll
            for (int na=0;na<4;na++) {
                int n = wn*32 + na*8;
                bf[na][0] = Bs[(kk+c  )*G_BS + n + r];
                bf[na][1] = Bs[(kk+c+4)*G_BS + n + r];
            }
#pragma unroll
            for (int ma=0;ma<4;ma++)
#pragma unroll
                for (int na=0;na<4;na++)
                    mma_tf32(acc[ma][na], af[ma], bf[na]);
        }

        if (!more) break;
        __syncthreads();
#pragma unroll
        for (int i=0;i<4;i++) {
            int f4 = tid + i*256;
            unsigned* ad = &As[(f4>>3)*G_AS + (f4&7)*4];
            ad[0]=f2tf32(pa[i].x); ad[1]=f2tf32(pa[i].y); ad[2]=f2tf32(pa[i].z); ad[3]=f2tf32(pa[i].w);
            unsigned* bd = &Bs[(f4>>5)*G_BS + (f4&31)*4];
            bd[0]=f2tf32(pb[i].x); bd[1]=f2tf32(pb[i].y); bd[2]=f2tf32(pb[i].z); bd[3]=f2tf32(pb[i].w);
        }
        __syncthreads();
    }

    // ---- epilogue ----
#pragma unroll
    for (int ma=0;ma<4;ma++) {
        int m = blockIdx.y*128 + wm*64 + ma*16 + r;
#pragma unroll
        for (int na=0;na<4;na++) {
            int n = blockIdx.x*128 + wn*32 + na*8 + 2*c;
            *(float2*)&C[(size_t)m*N + n]     = make_float2(acc[ma][na][0], acc[ma][na][1]);
            *(float2*)&C[(size_t)(m+8)*N + n] = make_float2(acc[ma][na][2], acc[ma][na][3]);
        }
    }
}

// ---------------- fp32 SGEMM (kept only for the skinny x@W_KR) ------------
template<int BM, int BN, int BK, int TM, int TN>
__global__ void __launch_bounds__((BM/TM)*(BN/TN))
sgemm_kernel(const float* __restrict__ A, const float* __restrict__ B,
             float* __restrict__ C, int M, int N, int K)
{
    constexpr int THREADS = (BM/TM)*(BN/TN);
    __shared__ float As[BK][BM];
    __shared__ float Bsm[BK][BN];
    const int tid = threadIdx.x;
    const int tx  = tid % (BN/TN);
    const int ty  = tid / (BN/TN);
    const float* Ab = A + (size_t)blockIdx.y * BM * K;
    const float* Bt = B + (size_t)blockIdx.x * BN;

    float acc[TM][TN];
#pragma unroll
    for (int i=0;i<TM;i++)
#pragma unroll
        for (int j=0;j<TN;j++) acc[i][j]=0.f;

    for (int k0 = 0; k0 < K; k0 += BK) {
#pragma unroll
        for (int i = tid; i < BM*BK; i += THREADS) {
            int rr = i / BK, cc = i % BK;
            As[cc][rr] = Ab[(size_t)rr*K + k0 + cc];
        }
#pragma unroll
        for (int i = tid; i < BK*BN; i += THREADS) {
            int rr = i / BN, cc = i % BN;
            Bsm[rr][cc] = Bt[(size_t)(k0+rr)*N + cc];
        }
        __syncthreads();
#pragma unroll
        for (int kk=0; kk<BK; kk++) {
            float ar[TM], br[TN];
#pragma unroll
            for (int i=0;i<TM;i+=4) {
                float4 v = *(const float4*)&As[kk][ty*TM+i];
                ar[i]=v.x; ar[i+1]=v.y; ar[i+2]=v.z; ar[i+3]=v.w;
            }
#pragma unroll
            for (int j=0;j<TN;j+=4) {
                float4 v = *(const float4*)&Bsm[kk][tx*TN+j];
                br[j]=v.x; br[j+1]=v.y; br[j+2]=v.z; br[j+3]=v.w;
            }
#pragma unroll
            for (int i=0;i<TM;i++)
#pragma unroll
                for (int j=0;j<TN;j++)
                    acc[i][j] += ar[i]*br[j];
        }
        __syncthreads();
    }
    float* Cb = C + (size_t)blockIdx.y*BM*N + (size_t)blockIdx.x*BN;
#pragma unroll
    for (int i=0;i<TM;i++)
#pragma unroll
        for (int j=0;j<TN;j+=4) {
            float4 v = make_float4(acc[i][j],acc[i][j+1],acc[i][j+2],acc[i][j+3]);
            *(float4*)&Cb[(size_t)(ty*TM+i)*N + tx*TN + j] = v;
        }
}

// ---------------- prep: RoPE + concat + normalize + scale + reshape ----------------
__global__ void __launch_bounds__(256) prep_kernel(const float* __restrict__ s_qk_ptr)
{
    const int bl = blockIdx.x;          // 0..8191  (= b*L + l)
    const int b  = bl >> 11;            // L = 2048
    const int l  = bl & 2047;
    const int t  = threadIdx.x;         // 256 threads

    __shared__ float cs[32], sn[32];
    __shared__ float krr[64];
    __shared__ float red[256];

    const float s_qk = *s_qk_ptr;

    if (t < 32) {
        float inv = powf(10000.0f, -2.0f * (float)t / 64.0f);
        float ang = (float)l * inv;
        cs[t] = cosf(ang);
        sn[t] = sinf(ang);
    }
    __syncthreads();

    if (t < 64) {
        int j = t & 31;
        float v   = g_kr[(size_t)bl*64 + t];
        float rot = (t < 32) ? -g_kr[(size_t)bl*64 + t + 32]
                             :  g_kr[(size_t)bl*64 + t - 32];
        krr[t] = v*cs[j] + rot*sn[j];
    }
    __syncthreads();

    for (int h = 0; h < NHh; h++) {
        const size_t off192 = ((size_t)(b*NHh + h)*Ll + l) * QKD;
        const size_t off128 = ((size_t)(b*NHh + h)*Ll + l) * DHh;

        float kv = 0.f;
        if (t < 128)      kv = g_kc[(size_t)bl*Dd + h*DHh + t];
        else if (t < 192) kv = krr[t-128];
        red[t] = kv*kv;
        __syncthreads();
        for (int s=128; s>0; s>>=1) { if (t<s) red[t]+=red[t+s]; __syncthreads(); }
        {
            float invn = 1.0f / fmaxf(sqrtf(red[0]), 1e-12f);
            if (t < 192) g_k[off192 + t] = kv * invn;
        }
        __syncthreads();

        float qv = 0.f;
        if (t < 128) qv = g_qc[(size_t)bl*Dd + h*DHh + t];
        else if (t < 192) {
            int j  = t - 128;
            int jj = j & 31;
            const float* qrp = g_qr + (size_t)bl*(NHh*DHRr) + h*DHRr;
            float v   = qrp[j];
            float rot = (j < 32) ? -qrp[j+32] : qrp[j-32];
            qv = v*cs[jj] + rot*sn[jj];
        }
        red[t] = qv*qv;
        __syncthreads();
        for (int s=128; s>0; s>>=1) { if (t<s) red[t]+=red[t+s]; __syncthreads(); }
        {
            float invq = s_qk / fmaxf(sqrtf(red[0]), 1e-12f);
            if (t < 192) g_q[off192 + t] = qv * invq;
        }
        if (t < 128) g_v[off128 + t] = g_vfl[(size_t)bl*Dd + h*DHh + t];
        __syncthreads();
    }
}

// ---------------- flash attention (fp32, causal, BQ=BK=64) ----------------
__global__ void __launch_bounds__(256) attn_kernel()
{
    extern __shared__ float sm[];
    float* Qs = sm;                   // [192][64]
    float* Ks = Qs + QKD*64;          // [192][64]
    float* Vs = Ks + QKD*64;          // [64][128]
    float* Ps = Vs + 64*128;          // [64][64]

    const int qt = (gridDim.x - 1) - blockIdx.x;
    const int bh = blockIdx.y;
    const int q0 = qt * 64;
    const float* Qg = g_q + (size_t)bh*Ll*QKD;
    const float* Kg = g_k + (size_t)bh*Ll*QKD;
    const float* Vg = g_v + (size_t)bh*Ll*DHh;

    const int tid = threadIdx.x;
    const int tx = tid & 15;
    const int ty = tid >> 4;

    for (int i = tid; i < 64*QKD; i += 256) {
        int r = i / QKD, d = i % QKD;
        Qs[d*64 + r] = Qg[(size_t)(q0 + r)*QKD + d];
    }

    float O[4][8];
    float m_i[4], l_i[4];
#pragma unroll
    for (int i=0;i<4;i++){
        m_i[i] = -1e30f; l_i[i] = 0.f;
#pragma unroll
        for (int j=0;j<8;j++) O[i][j]=0.f;
    }

    for (int kt = 0; kt <= qt; kt++) {
        const int k0 = kt * 64;
        for (int i = tid; i < 64*QKD; i += 256) {
            int r = i / QKD, d = i % QKD;
            Ks[d*64 + r] = Kg[(size_t)(k0 + r)*QKD + d];
        }
        for (int i = tid; i < 64*DHh; i += 256)
            Vs[i] = Vg[(size_t)k0*DHh + i];
        __syncthreads();

        float S[4][4];
#pragma unroll
        for (int i=0;i<4;i++)
#pragma unroll
            for (int j=0;j<4;j++) S[i][j]=0.f;

        for (int k = 0; k < QKD; k++) {
            float4 a = *(const float4*)&Qs[k*64 + ty*4];
            float4 b = *(const float4*)&Ks[k*64 + tx*4];
            float ar[4] = {a.x,a.y,a.z,a.w};
            float br[4] = {b.x,b.y,b.z,b.w};
#pragma unroll
            for (int i=0;i<4;i++)
#pragma unroll
                for (int j=0;j<4;j++)
                    S[i][j] += ar[i]*br[j];
        }

        if (kt == qt) {
#pragma unroll
            for (int i=0;i<4;i++)
#pragma unroll
                for (int j=0;j<4;j++)
                    if (tx*4+j > ty*4+i) S[i][j] = -1e30f;
        }

#pragma unroll
        for (int i=0;i<4;i++) {
            float mx = fmaxf(fmaxf(S[i][0],S[i][1]), fmaxf(S[i][2],S[i][3]));
#pragma unroll
            for (int o=8;o>0;o>>=1) mx = fmaxf(mx, __shfl_xor_sync(0xffffffffu, mx, o));
            float mnew = fmaxf(m_i[i], mx);
            float corr = __expf(m_i[i] - mnew);
            float rs = 0.f;
#pragma unroll
            for (int j=0;j<4;j++) {
                float p = __expf(S[i][j] - mnew);
                S[i][j] = p; rs += p;
            }
#pragma unroll
            for (int o=8;o>0;o>>=1) rs += __shfl_xor_sync(0xffffffffu, rs, o);
            l_i[i] = l_i[i]*corr + rs;
            m_i[i] = mnew;
#pragma unroll
            for (int j=0;j<8;j++) O[i][j] *= corr;
        }

#pragma unroll
        for (int i=0;i<4;i++)
            *(float4*)&Ps[(ty*4+i)*64 + tx*4] = make_float4(S[i][0],S[i][1],S[i][2],S[i][3]);
        __syncthreads();

        for (int k = 0; k < 64; k++) {
            float4 v0 = *(const float4*)&Vs[k*128 + tx*8];
            float4 v1 = *(const float4*)&Vs[k*128 + tx*8 + 4];
#pragma unroll
            for (int i=0;i<4;i++) {
                float p = Ps[(ty*4+i)*64 + k];
                O[i][0]+=p*v0.x; O[i][1]+=p*v0.y; O[i][2]+=p*v0.z; O[i][3]+=p*v0.w;
                O[i][4]+=p*v1.x; O[i][5]+=p*v1.y; O[i][6]+=p*v1.z; O[i][7]+=p*v1.w;
            }
        }
        __syncthreads();
    }

    const int b = bh >> 4, h = bh & 15;
#pragma unroll
    for (int i=0;i<4;i++) {
        float inv = 1.0f / l_i[i];
        int l = q0 + ty*4 + i;
        float* dst = g_ao + ((size_t)(b*Ll + l))*Dd + h*DHh + tx*8;
        float4 o0 = make_float4(O[i][0]*inv,O[i][1]*inv,O[i][2]*inv,O[i][3]*inv);
        float4 o1 = make_float4(O[i][4]*inv,O[i][5]*inv,O[i][6]*inv,O[i][7]*inv);
        *(float4*)&dst[0] = o0;
        *(float4*)&dst[4] = o1;
    }
}

// ---------------- launch ----------------
extern "C" void kernel_launch(void* const* d_in, const int* in_sizes, int n_in,
                              void* d_out, int out_size)
{
    const float* x     = (const float*)d_in[0];
    const float* W_DKV = (const float*)d_in[1];
    const float* W_UK  = (const float*)d_in[2];
    const float* W_UV  = (const float*)d_in[3];
    const float* W_DQ  = (const float*)d_in[4];
    const float* W_UQ  = (const float*)d_in[5];
    const float* W_QR  = (const float*)d_in[6];
    const float* W_KR  = (const float*)d_in[7];
    const float* W_O   = (const float*)d_in[8];
    const float* s_qk  = (const float*)d_in[9];
    float* out = (float*)d_out;

    float *ckv, *cq, *kr, *kc, *vfl, *qc, *qr, *ao;
    cudaGetSymbolAddress((void**)&ckv, g_ckv);
    cudaGetSymbolAddress((void**)&cq,  g_cq);
    cudaGetSymbolAddress((void**)&kr,  g_kr);
    cudaGetSymbolAddress((void**)&kc,  g_kc);
    cudaGetSymbolAddress((void**)&vfl, g_vfl);
    cudaGetSymbolAddress((void**)&qc,  g_qc);
    cudaGetSymbolAddress((void**)&qr,  g_qr);
    cudaGetSymbolAddress((void**)&ao,  g_ao);

    cudaFuncSetAttribute(attn_kernel, cudaFuncAttributeMaxDynamicSharedMemorySize,
                         (QKD*64 + QKD*64 + 64*128 + 64*64) * (int)sizeof(float));

    dim3 thr(256);

    // down / rope projections from x (tf32 tensor cores)
    tf32_gemm<<<dim3(DCc/128, Mtok/128), thr>>>(x, W_DKV, ckv, Mtok, DCc, Dd);
    tf32_gemm<<<dim3(DCc/128, Mtok/128), thr>>>(x, W_DQ,  cq,  Mtok, DCc, Dd);
    sgemm_kernel<64,64,8,4,4><<<dim3(1, Mtok/64), thr>>>(x, W_KR, kr, Mtok, DHRr, Dd);

    // up projections (tf32 tensor cores)
    tf32_gemm<<<dim3(Dd/128, Mtok/128), thr>>>(ckv, W_UK, kc,  Mtok, Dd,  DCc);
    tf32_gemm<<<dim3(Dd/128, Mtok/128), thr>>>(ckv, W_UV, vfl, Mtok, Dd,  DCc);
    tf32_gemm<<<dim3(Dd/128, Mtok/128), thr>>>(cq,  W_UQ, qc,  Mtok, Dd,  DCc);
    tf32_gemm<<<dim3((NHh*DHRr)/128, Mtok/128), thr>>>(cq, W_QR, qr, Mtok, NHh*DHRr, DCc);

    // rope + concat + normalize + reshape
    prep_kernel<<<Mtok, 256>>>(s_qk);

    // causal flash attention (fp32 — next round's target)
    size_t smem = (size_t)(QKD*64 + QKD*64 + 64*128 + 64*64) * sizeof(float);
    attn_kernel<<<dim3(Ll/64, Bb*NHh), 256, smem>>>();

    // output projection -> d_out (tf32 tensor cores)
    tf32_gemm<<<dim3(Dd/128, Mtok/128), thr>>>(ao, W_O, out, Mtok, Dd, Dd);
}

// round 3
// speedup vs baseline: 3.8856x; 2.1605x over previous
#include <cuda_runtime.h>
#include <cuda_bf16.h>
#include <math.h>

// ---------------- problem constants ----------------
#define Bb 4
#define Ll 2048
#define Dd 2048
#define NHh 16
#define DHh 128
#define DHRr 64
#define DCc 1024
#define Mtok (Bb*Ll)            // 8192
#define QKD 192                 // DH + DHR

// ---------------- device scratch (static, allocation-free) ----------------
__device__ float g_ckv [(size_t)Mtok*DCc];
__device__ float g_cq  [(size_t)Mtok*DCc];
__device__ float g_kr  [(size_t)Mtok*DHRr];
__device__ float g_kc  [(size_t)Mtok*Dd];
__device__ float g_vfl [(size_t)Mtok*Dd];
__device__ float g_qc  [(size_t)Mtok*Dd];
__device__ float g_qr  [(size_t)Mtok*(NHh*DHRr)];
__device__ float g_q   [(size_t)Bb*NHh*Ll*QKD];
__device__ float g_k   [(size_t)Bb*NHh*Ll*QKD];
__device__ float g_v   [(size_t)Bb*NHh*Ll*DHh];
__device__ float g_ao  [(size_t)Mtok*Dd];

// ---------------- tf32 helpers ----------------
__device__ __forceinline__ unsigned f2tf32(float f) {
    unsigned r;
    asm("cvt.rna.tf32.f32 %0, %1;" : "=r"(r) : "f"(f));
    return r;
}

__device__ __forceinline__ void mma_tf32(float* d, const unsigned* a, const unsigned* b) {
    asm volatile(
        "mma.sync.aligned.m16n8k8.row.col.f32.tf32.tf32.f32 "
        "{%0,%1,%2,%3}, {%4,%5,%6,%7}, {%8,%9}, {%0,%1,%2,%3};"
        : "+f"(d[0]), "+f"(d[1]), "+f"(d[2]), "+f"(d[3])
        : "r"(a[0]), "r"(a[1]), "r"(a[2]), "r"(a[3]), "r"(b[0]), "r"(b[1]));
}

// ---------------- tf32 tensor-core GEMM: C = A(MxK) * B(KxN), row-major ----
// 128x128x32 CTA tile, 8 warps (2x4), 64x32 warp tile, m16n8k8 atoms
// N may be < 128 (single col-block grid) -> guarded B loads / C stores.
#define G_AS 36
#define G_BS 136
__global__ void __launch_bounds__(256)
tf32_gemm(const float* __restrict__ A, const float* __restrict__ B,
          float* __restrict__ C, int M, int N, int K)
{
    __shared__ unsigned As[128*G_AS];
    __shared__ unsigned Bs[32*G_BS];

    const int tid  = threadIdx.x;
    const int lane = tid & 31;
    const int warp = tid >> 5;
    const int wm = warp >> 2;
    const int wn = warp & 3;
    const int r = lane >> 2;
    const int c = lane & 3;

    const float* Ag = A + (size_t)blockIdx.y * 128 * K;
    const float* Bg = B + (size_t)blockIdx.x * 128;

    float acc[4][4][4];
#pragma unroll
    for (int i=0;i<4;i++)
#pragma unroll
        for (int j=0;j<4;j++)
#pragma unroll
            for (int t=0;t<4;t++) acc[i][j][t]=0.f;

    float4 pa[4], pb[4];
    const float4 zf4 = make_float4(0.f,0.f,0.f,0.f);

#pragma unroll
    for (int i=0;i<4;i++) {
        int f4 = tid + i*256;
        pa[i] = *(const float4*)&Ag[(size_t)(f4>>3)*K + (f4&7)*4];
        int bc = (f4&31)*4;
        pb[i] = (bc < N) ? *(const float4*)&Bg[(size_t)(f4>>5)*N + bc] : zf4;
    }
#pragma unroll
    for (int i=0;i<4;i++) {
        int f4 = tid + i*256;
        unsigned* ad = &As[(f4>>3)*G_AS + (f4&7)*4];
        ad[0]=f2tf32(pa[i].x); ad[1]=f2tf32(pa[i].y); ad[2]=f2tf32(pa[i].z); ad[3]=f2tf32(pa[i].w);
        unsigned* bd = &Bs[(f4>>5)*G_BS + (f4&31)*4];
        bd[0]=f2tf32(pb[i].x); bd[1]=f2tf32(pb[i].y); bd[2]=f2tf32(pb[i].z); bd[3]=f2tf32(pb[i].w);
    }
    __syncthreads();

    for (int k0 = 32; ; k0 += 32) {
        const bool more = (k0 < K);
        if (more) {
#pragma unroll
            for (int i=0;i<4;i++) {
                int f4 = tid + i*256;
                pa[i] = *(const float4*)&Ag[(size_t)(f4>>3)*K + k0 + (f4&7)*4];
                int bc = (f4&31)*4;
                pb[i] = (bc < N) ? *(const float4*)&Bg[(size_t)(k0 + (f4>>5))*N + bc] : zf4;
            }
        }

#pragma unroll
        for (int kk=0; kk<32; kk+=8) {
            unsigned af[4][4], bf[4][2];
#pragma unroll
            for (int ma=0;ma<4;ma++) {
                int m = wm*64 + ma*16;
                af[ma][0] = As[(m+r  )*G_AS + kk + c  ];
                af[ma][1] = As[(m+r+8)*G_AS + kk + c  ];
                af[ma][2] = As[(m+r  )*G_AS + kk + c+4];
                af[ma][3] = As[(m+r+8)*G_AS + kk + c+4];
            }
#pragma unroll
            for (int na=0;na<4;na++) {
                int n = wn*32 + na*8;
                bf[na][0] = Bs[(kk+c  )*G_BS + n + r];
                bf[na][1] = Bs[(kk+c+4)*G_BS + n + r];
            }
#pragma unroll
            for (int ma=0;ma<4;ma++)
#pragma unroll
                for (int na=0;na<4;na++)
                    mma_tf32(acc[ma][na], af[ma], bf[na]);
        }

        if (!more) break;
        __syncthreads();
#pragma unroll
        for (int i=0;i<4;i++) {
            int f4 = tid + i*256;
            unsigned* ad = &As[(f4>>3)*G_AS + (f4&7)*4];
            ad[0]=f2tf32(pa[i].x); ad[1]=f2tf32(pa[i].y); ad[2]=f2tf32(pa[i].z); ad[3]=f2tf32(pa[i].w);
            unsigned* bd = &Bs[(f4>>5)*G_BS + (f4&31)*4];
            bd[0]=f2tf32(pb[i].x); bd[1]=f2tf32(pb[i].y); bd[2]=f2tf32(pb[i].z); bd[3]=f2tf32(pb[i].w);
        }
        __syncthreads();
    }

#pragma unroll
    for (int ma=0;ma<4;ma++) {
        int m = blockIdx.y*128 + wm*64 + ma*16 + r;
#pragma unroll
        for (int na=0;na<4;na++) {
            int n = blockIdx.x*128 + wn*32 + na*8 + 2*c;
            if (n < N) {
                *(float2*)&C[(size_t)m*N + n]     = make_float2(acc[ma][na][0], acc[ma][na][1]);
                *(float2*)&C[(size_t)(m+8)*N + n] = make_float2(acc[ma][na][2], acc[ma][na][3]);
            }
        }
    }
}

// ---------------- prep: RoPE + concat + normalize + scale + reshape ----------------
__global__ void __launch_bounds__(256) prep_kernel(const float* __restrict__ s_qk_ptr)
{
    const int bl = blockIdx.x;
    const int b  = bl >> 11;
    const int l  = bl & 2047;
    const int t  = threadIdx.x;

    __shared__ float cs[32], sn[32];
    __shared__ float krr[64];
    __shared__ float red[256];

    const float s_qk = *s_qk_ptr;

    if (t < 32) {
        float inv = powf(10000.0f, -2.0f * (float)t / 64.0f);
        float ang = (float)l * inv;
        cs[t] = cosf(ang);
        sn[t] = sinf(ang);
    }
    __syncthreads();

    if (t < 64) {
        int j = t & 31;
        float v   = g_kr[(size_t)bl*64 + t];
        float rot = (t < 32) ? -g_kr[(size_t)bl*64 + t + 32]
                             :  g_kr[(size_t)bl*64 + t - 32];
        krr[t] = v*cs[j] + rot*sn[j];
    }
    __syncthreads();

    for (int h = 0; h < NHh; h++) {
        const size_t off192 = ((size_t)(b*NHh + h)*Ll + l) * QKD;
        const size_t off128 = ((size_t)(b*NHh + h)*Ll + l) * DHh;

        float kv = 0.f;
        if (t < 128)      kv = g_kc[(size_t)bl*Dd + h*DHh + t];
        else if (t < 192) kv = krr[t-128];
        red[t] = kv*kv;
        __syncthreads();
        for (int s=128; s>0; s>>=1) { if (t<s) red[t]+=red[t+s]; __syncthreads(); }
        {
            float invn = 1.0f / fmaxf(sqrtf(red[0]), 1e-12f);
            if (t < 192) g_k[off192 + t] = kv * invn;
        }
        __syncthreads();

        float qv = 0.f;
        if (t < 128) qv = g_qc[(size_t)bl*Dd + h*DHh + t];
        else if (t < 192) {
            int j  = t - 128;
            int jj = j & 31;
            const float* qrp = g_qr + (size_t)bl*(NHh*DHRr) + h*DHRr;
            float v   = qrp[j];
            float rot = (j < 32) ? -qrp[j+32] : qrp[j-32];
            qv = v*cs[jj] + rot*sn[jj];
        }
        red[t] = qv*qv;
        __syncthreads();
        for (int s=128; s>0; s>>=1) { if (t<s) red[t]+=red[t+s]; __syncthreads(); }
        {
            float invq = s_qk / fmaxf(sqrtf(red[0]), 1e-12f);
            if (t < 192) g_q[off192 + t] = qv * invq;
        }
        if (t < 128) g_v[off128 + t] = g_vfl[(size_t)bl*Dd + h*DHh + t];
        __syncthreads();
    }
}

// ---------------- tf32 flash attention (causal, BQ=128, BK=64) ------------
// 8 warps; warp w owns S rows [w*16, w*16+16) x all 64 cols -> warp-local softmax.
// smem strides (u32): Q 196, K 196, V 132, P 68  (all fragment LDS conflict-free)
#define AQ_S 196
#define AV_S 132
#define AP_S 68
__global__ void __launch_bounds__(256, 1) attn_tf32_kernel()
{
    extern __shared__ unsigned smu[];
    unsigned* Qs = smu;                 // [128][196]
    unsigned* Ks = Qs + 128*AQ_S;       // [64][196]
    unsigned* Vs = Ks + 64*AQ_S;        // [64][132]
    unsigned* Ps = Vs + 64*AV_S;        // [128][68]

    const int qt = (gridDim.x - 1) - blockIdx.x;   // heavy blocks first
    const int bh = blockIdx.y;
    const int q0 = qt * 128;
    const float* Qg = g_q + (size_t)bh*Ll*QKD + (size_t)q0*QKD;
    const float* Kg = g_k + (size_t)bh*Ll*QKD;
    const float* Vg = g_v + (size_t)bh*Ll*DHh;

    const int tid  = threadIdx.x;
    const int lane = tid & 31;
    const int warp = tid >> 5;
    const int r = lane >> 2;
    const int c = lane & 3;
    const int m0 = warp * 16;

    // load Q tile (convert to tf32)
    for (int i = tid; i < 128*48; i += 256) {
        int row = i / 48, f = (i % 48) * 4;
        float4 v = *(const float4*)&Qg[(size_t)row*QKD + f];
        unsigned* d = &Qs[row*AQ_S + f];
        d[0]=f2tf32(v.x); d[1]=f2tf32(v.y); d[2]=f2tf32(v.z); d[3]=f2tf32(v.w);
    }

    float O[16][4];
#pragma unroll
    for (int nb=0; nb<16; nb++)
#pragma unroll
        for (int t=0; t<4; t++) O[nb][t] = 0.f;
    float m_i[2] = {-1e30f, -1e30f};
    float l_i[2] = {0.f, 0.f};

    const int nkt = 2*(qt+1);
    for (int kt = 0; kt < nkt; kt++) {
        const int k0 = kt*64;
        __syncthreads();   // prev iter's MMA reads done before overwriting K/V
        for (int i = tid; i < 64*48; i += 256) {
            int row = i / 48, f = (i % 48) * 4;
            float4 v = *(const float4*)&Kg[(size_t)(k0+row)*QKD + f];
            unsigned* d = &Ks[row*AQ_S + f];
            d[0]=f2tf32(v.x); d[1]=f2tf32(v.y); d[2]=f2tf32(v.z); d[3]=f2tf32(v.w);
        }
        for (int i = tid; i < 64*32; i += 256) {
            int row = i / 32, f = (i % 32) * 4;
            float4 v = *(const float4*)&Vg[(size_t)(k0+row)*DHh + f];
            unsigned* d = &Vs[row*AV_S + f];
            d[0]=f2tf32(v.x); d[1]=f2tf32(v.y); d[2]=f2tf32(v.z); d[3]=f2tf32(v.w);
        }
        __syncthreads();

        // ---- S = Q K^T (warp-local m16 x n64) ----
        float S[8][4];
#pragma unroll
        for (int j=0;j<8;j++)
#pragma unroll
            for (int t=0;t<4;t++) S[j][t]=0.f;

#pragma unroll 4
        for (int kk = 0; kk < QKD; kk += 8) {
            unsigned a[4];
            a[0] = Qs[(m0+r  )*AQ_S + kk + c  ];
            a[1] = Qs[(m0+r+8)*AQ_S + kk + c  ];
            a[2] = Qs[(m0+r  )*AQ_S + kk + c+4];
            a[3] = Qs[(m0+r+8)*AQ_S + kk + c+4];
#pragma unroll
            for (int j = 0; j < 8; j++) {
                unsigned b[2];
                b[0] = Ks[(j*8+r)*AQ_S + kk + c  ];
                b[1] = Ks[(j*8+r)*AQ_S + kk + c+4];
                mma_tf32(S[j], a, b);
            }
        }

        // ---- causal mask (only tiles overlapping the diagonal) ----
        if (kt >= nkt - 2) {
            const int row0 = q0 + m0 + r;
            const int row1 = row0 + 8;
#pragma unroll
            for (int j = 0; j < 8; j++) {
                int col = k0 + j*8 + 2*c;
                if (col   > row0) S[j][0] = -1e30f;
                if (col+1 > row0) S[j][1] = -1e30f;
                if (col   > row1) S[j][2] = -1e30f;
                if (col+1 > row1) S[j][3] = -1e30f;
            }
        }

        // ---- online softmax (rows r and r+8; stats across 4 c-lanes) ----
        float mx0 = -1e30f, mx1 = -1e30f;
#pragma unroll
        for (int j=0;j<8;j++) {
            mx0 = fmaxf(mx0, fmaxf(S[j][0], S[j][1]));
            mx1 = fmaxf(mx1, fmaxf(S[j][2], S[j][3]));
        }
        mx0 = fmaxf(mx0, __shfl_xor_sync(0xffffffffu, mx0, 1));
        mx0 = fmaxf(mx0, __shfl_xor_sync(0xffffffffu, mx0, 2));
        mx1 = fmaxf(mx1, __shfl_xor_sync(0xffffffffu, mx1, 1));
        mx1 = fmaxf(mx1, __shfl_xor_sync(0xffffffffu, mx1, 2));

        float mn0 = fmaxf(m_i[0], mx0), mn1 = fmaxf(m_i[1], mx1);
        float corr0 = __expf(m_i[0]-mn0), corr1 = __expf(m_i[1]-mn1);
        float rs0 = 0.f, rs1 = 0.f;
#pragma unroll
        for (int j=0;j<8;j++) {
            S[j][0] = __expf(S[j][0]-mn0); rs0 += S[j][0];
            S[j][1] = __expf(S[j][1]-mn0); rs0 += S[j][1];
            S[j][2] = __expf(S[j][2]-mn1); rs1 += S[j][2];
            S[j][3] = __expf(S[j][3]-mn1); rs1 += S[j][3];
        }
        rs0 += __shfl_xor_sync(0xffffffffu, rs0, 1);
        rs0 += __shfl_xor_sync(0xffffffffu, rs0, 2);
        rs1 += __shfl_xor_sync(0xffffffffu, rs1, 1);
        rs1 += __shfl_xor_sync(0xffffffffu, rs1, 2);
        l_i[0] = l_i[0]*corr0 + rs0;  m_i[0] = mn0;
        l_i[1] = l_i[1]*corr1 + rs1;  m_i[1] = mn1;

#pragma unroll
        for (int nb=0; nb<16; nb++) {
            O[nb][0]*=corr0; O[nb][1]*=corr0;
            O[nb][2]*=corr1; O[nb][3]*=corr1;
        }

        // ---- stage P (tf32) into own-warp rows of Ps ----
#pragma unroll
        for (int j=0;j<8;j++) {
            uint2 p0, p1;
            p0.x = f2tf32(S[j][0]); p0.y = f2tf32(S[j][1]);
            p1.x = f2tf32(S[j][2]); p1.y = f2tf32(S[j][3]);
            *(uint2*)&Ps[(m0+r  )*AP_S + j*8 + 2*c] = p0;
            *(uint2*)&Ps[(m0+r+8)*AP_S + j*8 + 2*c] = p1;
        }
        __syncwarp();

        // ---- O += P @ V ----
#pragma unroll
        for (int kc = 0; kc < 64; kc += 8) {
            unsigned a[4];
            a[0] = Ps[(m0+r  )*AP_S + kc + c  ];
            a[1] = Ps[(m0+r+8)*AP_S + kc + c  ];
            a[2] = Ps[(m0+r  )*AP_S + kc + c+4];
            a[3] = Ps[(m0+r+8)*AP_S + kc + c+4];
#pragma unroll
            for (int nb = 0; nb < 16; nb++) {
                unsigned b[2];
                b[0] = Vs[(kc+c  )*AV_S + nb*8 + r];
                b[1] = Vs[(kc+c+4)*AV_S + nb*8 + r];
                mma_tf32(O[nb], a, b);
            }
        }
    }

    // ---- epilogue: normalize and write to (B*L, NH*DH) ----
    const int b = bh >> 4, h = bh & 15;
    const float inv0 = 1.0f / l_i[0];
    const float inv1 = 1.0f / l_i[1];
    const int l0 = q0 + m0 + r;
    float* d0 = g_ao + ((size_t)(b*Ll + l0    ))*Dd + h*DHh;
    float* d1 = g_ao + ((size_t)(b*Ll + l0 + 8))*Dd + h*DHh;
#pragma unroll
    for (int nb=0; nb<16; nb++) {
        *(float2*)&d0[nb*8 + 2*c] = make_float2(O[nb][0]*inv0, O[nb][1]*inv0);
        *(float2*)&d1[nb*8 + 2*c] = make_float2(O[nb][2]*inv1, O[nb][3]*inv1);
    }
}

// ---------------- launch ----------------
extern "C" void kernel_launch(void* const* d_in, const int* in_sizes, int n_in,
                              void* d_out, int out_size)
{
    const float* x     = (const float*)d_in[0];
    const float* W_DKV = (const float*)d_in[1];
    const float* W_UK  = (const float*)d_in[2];
    const float* W_UV  = (const float*)d_in[3];
    const float* W_DQ  = (const float*)d_in[4];
    const float* W_UQ  = (const float*)d_in[5];
    const float* W_QR  = (const float*)d_in[6];
    const float* W_KR  = (const float*)d_in[7];
    const float* W_O   = (const float*)d_in[8];
    const float* s_qk  = (const float*)d_in[9];
    float* out = (float*)d_out;

    float *ckv, *cq, *kr, *kc, *vfl, *qc, *qr, *ao;
    cudaGetSymbolAddress((void**)&ckv, g_ckv);
    cudaGetSymbolAddress((void**)&cq,  g_cq);
    cudaGetSymbolAddress((void**)&kr,  g_kr);
    cudaGetSymbolAddress((void**)&kc,  g_kc);
    cudaGetSymbolAddress((void**)&vfl, g_vfl);
    cudaGetSymbolAddress((void**)&qc,  g_qc);
    cudaGetSymbolAddress((void**)&qr,  g_qr);
    cudaGetSymbolAddress((void**)&ao,  g_ao);

    const int attn_smem = (128*AQ_S + 64*AQ_S + 64*AV_S + 128*AP_S) * (int)sizeof(unsigned);
    cudaFuncSetAttribute(attn_tf32_kernel, cudaFuncAttributeMaxDynamicSharedMemorySize, attn_smem);

    dim3 thr(256);

    // down / rope projections from x (tf32 tensor cores)
    tf32_gemm<<<dim3(DCc/128, Mtok/128), thr>>>(x, W_DKV, ckv, Mtok, DCc, Dd);
    tf32_gemm<<<dim3(DCc/128, Mtok/128), thr>>>(x, W_DQ,  cq,  Mtok, DCc, Dd);
    tf32_gemm<<<dim3(1,        Mtok/128), thr>>>(x, W_KR,  kr,  Mtok, DHRr, Dd);

    // up projections (tf32 tensor cores)
    tf32_gemm<<<dim3(Dd/128, Mtok/128), thr>>>(ckv, W_UK, kc,  Mtok, Dd,  DCc);
    tf32_gemm<<<dim3(Dd/128, Mtok/128), thr>>>(ckv, W_UV, vfl, Mtok, Dd,  DCc);
    tf32_gemm<<<dim3(Dd/128, Mtok/128), thr>>>(cq,  W_UQ, qc,  Mtok, Dd,  DCc);
    tf32_gemm<<<dim3((NHh*DHRr)/128, Mtok/128), thr>>>(cq, W_QR, qr, Mtok, NHh*DHRr, DCc);

    // rope + concat + normalize + reshape
    prep_kernel<<<Mtok, 256>>>(s_qk);

    // causal flash attention (tf32 tensor cores)
    attn_tf32_kernel<<<dim3(Ll/128, Bb*NHh), thr, attn_smem>>>();

    // output projection -> d_out (tf32 tensor cores)
    tf32_gemm<<<dim3(Dd/128, Mtok/128), thr>>>(ao, W_O, out, Mtok, Dd, Dd);
}

// round 5
// speedup vs baseline: 5.6819x; 1.4623x over previous
#include <cuda_runtime.h>
#include <cuda_fp16.h>
#include <math.h>

// ---------------- problem constants ----------------
#define Bb 4
#define Ll 2048
#define Dd 2048
#define NHh 16
#define DHh 128
#define DHRr 64
#define DCc 1024
#define Mtok (Bb*Ll)            // 8192
#define QKD 192                 // DH + DHR

// ---------------- device scratch (static, allocation-free) ----------------
__device__ __half g_xh   [(size_t)Mtok*Dd];
__device__ __half g_wdkvT[(size_t)DCc*Dd];
__device__ __half g_wdqT [(size_t)DCc*Dd];
__device__ __half g_wkrT [(size_t)DHRr*Dd];
__device__ __half g_wukT [(size_t)Dd*DCc];
__device__ __half g_wuvT [(size_t)Dd*DCc];
__device__ __half g_wuqT [(size_t)Dd*DCc];
__device__ __half g_wqrT [(size_t)(NHh*DHRr)*DCc];
__device__ __half g_woT  [(size_t)Dd*Dd];
__device__ __half g_ckv  [(size_t)Mtok*DCc];
__device__ __half g_cq   [(size_t)Mtok*DCc];
__device__ __half g_kr   [(size_t)Mtok*DHRr];
__device__ __half g_kc   [(size_t)Mtok*Dd];
__device__ __half g_vfl  [(size_t)Mtok*Dd];
__device__ __half g_qc   [(size_t)Mtok*Dd];
__device__ __half g_qr   [(size_t)Mtok*(NHh*DHRr)];
__device__ __half g_q    [(size_t)Bb*NHh*Ll*QKD];
__device__ __half g_k    [(size_t)Bb*NHh*Ll*QKD];
__device__ __half g_vt   [(size_t)Bb*NHh*DHh*Ll];   // [bh][d][l]
__device__ __half g_ao   [(size_t)Mtok*Dd];

// ---------------- fp16 mma helper ----------------
__device__ __forceinline__ void mma_h16(float* d, const unsigned* a, const unsigned* b) {
    asm volatile(
        "mma.sync.aligned.m16n8k16.row.col.f32.f16.f16.f32 "
        "{%0,%1,%2,%3}, {%4,%5,%6,%7}, {%8,%9}, {%0,%1,%2,%3};"
        : "+f"(d[0]), "+f"(d[1]), "+f"(d[2]), "+f"(d[3])
        : "r"(a[0]), "r"(a[1]), "r"(a[2]), "r"(a[3]), "r"(b[0]), "r"(b[1]));
}

// ---------------- pre-pass: x fp32 -> fp16 ----------------
__global__ void __launch_bounds__(256) cvt_x(const float* __restrict__ x, __half* __restrict__ xh, int n4)
{
    int i = blockIdx.x*256 + threadIdx.x;
    if (i < n4) {
        float4 v = ((const float4*)x)[i];
        __half2* o = (__half2*)xh;
        o[2*i]   = __floats2half2_rn(v.x, v.y);
        o[2*i+1] = __floats2half2_rn(v.z, v.w);
    }
}

// ---------------- pre-pass: W [K][N] fp32 -> Wt [N][K] fp16 ----------------
__global__ void __launch_bounds__(256) wtrans(const float* __restrict__ W, __half* __restrict__ Wt,
                                              int K, int N)
{
    __shared__ __half t[32][33];
    const int n0 = blockIdx.x*32, k0 = blockIdx.y*32;
    const int tx = threadIdx.x & 31, ty = threadIdx.x >> 5;   // 32x8
#pragma unroll
    for (int i=0;i<4;i++)
        t[ty+i*8][tx] = __float2half(W[(size_t)(k0+ty+i*8)*N + n0+tx]);
    __syncthreads();
#pragma unroll
    for (int i=0;i<4;i++)
        Wt[(size_t)(n0+ty+i*8)*K + k0+tx] = t[tx][ty+i*8];
}

// ---------------- fp16 tensor-core GEMM: C[M][N] = A[M][K] * Bt[N][K]^T ----
// 128x128x32 CTA tile, 8 warps (2x4), 64x32 warp tile, m16n8k16 atoms.
// Both operand tiles k-major in smem, stride 20 words per row (conflict-free frags).
#define HS 20
template<bool OUTF32>
__global__ void __launch_bounds__(256)
h16_gemm(const __half* __restrict__ A, const __half* __restrict__ Bt,
         void* __restrict__ Cv, int M, int N, int K)
{
    __shared__ unsigned As[128*HS];
    __shared__ unsigned Bs[128*HS];

    const int tid  = threadIdx.x;
    const int lane = tid & 31;
    const int warp = tid >> 5;
    const int wm = warp >> 2, wn = warp & 3;
    const int r = lane >> 2,  c = lane & 3;

    const __half* Ag = A  + (size_t)blockIdx.y * 128 * K;
    const __half* Bg = Bt + (size_t)blockIdx.x * 128 * K;
    const int nrem = N - blockIdx.x*128;

    const int arow  = tid >> 2;          // 0..63
    const int arow2 = arow + 64;
    const int ach   = tid & 3;           // 8-half chunk
    const int brow  = (arow  < nrem) ? arow  : (nrem-1);
    const int brow2 = (arow2 < nrem) ? arow2 : (nrem-1);

    float acc[4][4][4];
#pragma unroll
    for (int i=0;i<4;i++)
#pragma unroll
        for (int j=0;j<4;j++)
#pragma unroll
            for (int t=0;t<4;t++) acc[i][j][t]=0.f;

    uint4 pa0, pa1, pb0, pb1;
    pa0 = *(const uint4*)(Ag + (size_t)arow *K + ach*8);
    pa1 = *(const uint4*)(Ag + (size_t)arow2*K + ach*8);
    pb0 = *(const uint4*)(Bg + (size_t)brow *K + ach*8);
    pb1 = *(const uint4*)(Bg + (size_t)brow2*K + ach*8);
    *(uint4*)&As[arow *HS + ach*4] = pa0;
    *(uint4*)&As[arow2*HS + ach*4] = pa1;
    *(uint4*)&Bs[arow *HS + ach*4] = pb0;
    *(uint4*)&Bs[arow2*HS + ach*4] = pb1;
    __syncthreads();

    for (int k0 = 32; ; k0 += 32) {
        const bool more = (k0 < K);
        if (more) {
            pa0 = *(const uint4*)(Ag + (size_t)arow *K + k0 + ach*8);
            pa1 = *(const uint4*)(Ag + (size_t)arow2*K + k0 + ach*8);
            pb0 = *(const uint4*)(Bg + (size_t)brow *K + k0 + ach*8);
            pb1 = *(const uint4*)(Bg + (size_t)brow2*K + k0 + ach*8);
        }

#pragma unroll
        for (int kc8 = 0; kc8 < 16; kc8 += 8) {    // two k16 chunks
            unsigned af[4][4], bf[4][2];
#pragma unroll
            for (int ma=0;ma<4;ma++) {
                int m = wm*64 + ma*16;
                af[ma][0] = As[(m+r  )*HS + kc8 + c  ];
                af[ma][1] = As[(m+r+8)*HS + kc8 + c  ];
                af[ma][2] = As[(m+r  )*HS + kc8 + c+4];
                af[ma][3] = As[(m+r+8)*HS + kc8 + c+4];
            }
#pragma unroll
            for (int na=0;na<4;na++) {
                int n = wn*32 + na*8;
                bf[na][0] = Bs[(n+r)*HS + kc8 + c  ];
                bf[na][1] = Bs[(n+r)*HS + kc8 + c+4];
            }
#pragma unroll
            for (int ma=0;ma<4;ma++)
#pragma unroll
                for (int na=0;na<4;na++)
                    mma_h16(acc[ma][na], af[ma], bf[na]);
        }

        if (!more) break;
        __syncthreads();
        *(uint4*)&As[arow *HS + ach*4] = pa0;
        *(uint4*)&As[arow2*HS + ach*4] = pa1;
        *(uint4*)&Bs[arow *HS + ach*4] = pb0;
        *(uint4*)&Bs[arow2*HS + ach*4] = pb1;
        __syncthreads();
    }

#pragma unroll
    for (int ma=0;ma<4;ma++) {
        int m = blockIdx.y*128 + wm*64 + ma*16 + r;
#pragma unroll
        for (int na=0;na<4;na++) {
            int n = blockIdx.x*128 + wn*32 + na*8 + 2*c;
            if (n < N) {
                if (OUTF32) {
                    float* C = (float*)Cv;
                    *(float2*)&C[(size_t)m*N + n]     = make_float2(acc[ma][na][0], acc[ma][na][1]);
                    *(float2*)&C[(size_t)(m+8)*N + n] = make_float2(acc[ma][na][2], acc[ma][na][3]);
                } else {
                    __half* C = (__half*)Cv;
                    *(__half2*)&C[(size_t)m*N + n]     = __floats2half2_rn(acc[ma][na][0], acc[ma][na][1]);
                    *(__half2*)&C[(size_t)(m+8)*N + n] = __floats2half2_rn(acc[ma][na][2], acc[ma][na][3]);
                }
            }
        }
    }
}

// ---------------- V transpose: g_vfl [bl][h*128+d] -> g_vt [bh][d][l] ------
__global__ void __launch_bounds__(256) vtrans()
{
    __shared__ __half t[64][DHh+8];       // [l][d], stride 136 halves
    const int bh = blockIdx.y, b = bh >> 4, h = bh & 15;
    const int l0 = blockIdx.x * 64;
    const int tid = threadIdx.x;

    for (int i = tid; i < 64*16; i += 256) {
        int l = i >> 4, ch = i & 15;
        *(uint4*)&t[l][ch*8] =
            *(const uint4*)(g_vfl + ((size_t)(b*Ll + l0 + l))*Dd + h*DHh + ch*8);
    }
    __syncthreads();
    for (int i = tid; i < 128*8; i += 256) {
        int d = i >> 3, ch = i & 7;
        __half2 p[4];
#pragma unroll
        for (int u=0;u<4;u++) {
            int l = ch*8 + u*2;
            p[u] = __halves2half2(t[l][d], t[l+1][d]);
        }
        *(uint4*)(g_vt + (size_t)bh*DHh*Ll + (size_t)d*Ll + l0 + ch*8) = *(uint4*)p;
    }
}

// ---------------- prep: RoPE + concat + normalize + scale ------------------
// one block per (token, head); 192 threads; single __syncthreads
__global__ void __launch_bounds__(192) prep2(const float* __restrict__ s_qk_ptr)
{
    const int bl = blockIdx.x, h = blockIdx.y;
    const int b = bl >> 11, l = bl & 2047;
    const int t = threadIdx.x;

    __shared__ float red[2][6];
    const float s_qk = *s_qk_ptr;

    float kv, qv;
    if (t < 128) {
        kv = __half2float(g_kc[(size_t)bl*Dd + h*DHh + t]);
        qv = __half2float(g_qc[(size_t)bl*Dd + h*DHh + t]);
    } else {
        int j = t - 128, jj = j & 31;
        float inv = powf(10000.0f, -(float)jj/32.0f);
        float ang = (float)l * inv;
        float csv = cosf(ang), snv = sinf(ang);
        {
            float v  = __half2float(g_kr[(size_t)bl*DHRr + j]);
            float vo = __half2float(g_kr[(size_t)bl*DHRr + (j<32 ? j+32 : j-32)]);
            float rot = (j<32) ? -vo : vo;
            kv = v*csv + rot*snv;
        }
        {
            const __half* qrp = g_qr + (size_t)bl*(NHh*DHRr) + h*DHRr;
            float v  = __half2float(qrp[j]);
            float vo = __half2float(qrp[(j<32 ? j+32 : j-32)]);
            float rot = (j<32) ? -vo : vo;
            qv = v*csv + rot*snv;
        }
    }

    float ks = kv*kv, qs = qv*qv;
#pragma unroll
    for (int o=16;o>0;o>>=1) {
        ks += __shfl_xor_sync(0xffffffffu, ks, o);
        qs += __shfl_xor_sync(0xffffffffu, qs, o);
    }
    const int w = t >> 5;
    if ((t & 31) == 0) { red[0][w] = ks; red[1][w] = qs; }
    __syncthreads();
    float ksum = red[0][0]+red[0][1]+red[0][2]+red[0][3]+red[0][4]+red[0][5];
    float qsum = red[1][0]+red[1][1]+red[1][2]+red[1][3]+red[1][4]+red[1][5];
    float invk = 1.0f / fmaxf(sqrtf(ksum), 1e-12f);
    float invq = s_qk / fmaxf(sqrtf(qsum), 1e-12f);

    size_t off = ((size_t)(b*NHh + h)*Ll + l)*QKD + t;
    g_k[off] = __float2half(kv*invk);
    g_q[off] = __float2half(qv*invq);
}

// ---------------- fp16 flash attention (causal, BQ=128, BK=64) -------------
// 8 warps; warp w owns rows [w*16, w*16+16); warp-local softmax.
// word strides: Q/K 100, V/P 36 (conflict-free fragment LDS)
#define QS 100
#define VS 36
__global__ void __launch_bounds__(256, 1) attn_h16()
{
    extern __shared__ unsigned smu[];
    unsigned* Qs = smu;                 // [128][100]
    unsigned* Ks = Qs + 128*QS;         // [64][100]
    unsigned* Vs = Ks + 64*QS;          // [128 d][36]   (k = l along words)
    unsigned* Ps = Vs + 128*VS;         // [128][36]

    const int qt = (gridDim.x - 1) - blockIdx.x;   // heavy blocks first
    const int bh = blockIdx.y;
    const int q0 = qt * 128;
    const __half* Qg = g_q  + (size_t)bh*Ll*QKD + (size_t)q0*QKD;
    const __half* Kg = g_k  + (size_t)bh*Ll*QKD;
    const __half* Vg = g_vt + (size_t)bh*DHh*Ll;

    const int tid  = threadIdx.x;
    const int lane = tid & 31;
    const int warp = tid >> 5;
    const int r = lane >> 2, c = lane & 3;
    const int m0 = warp * 16;

    for (int i = tid; i < 128*24; i += 256) {
        int row = i / 24, ch = i % 24;
        *(uint4*)&Qs[row*QS + ch*4] = *(const uint4*)(Qg + (size_t)row*QKD + ch*8);
    }

    float O[16][4];
#pragma unroll
    for (int nb=0; nb<16; nb++)
#pragma unroll
        for (int t=0; t<4; t++) O[nb][t] = 0.f;
    float m_i[2] = {-1e30f, -1e30f};
    float l_i[2] = {0.f, 0.f};

    const int nkt = 2*(qt+1);
    for (int kt = 0; kt < nkt; kt++) {
        const int k0 = kt*64;
        __syncthreads();
        for (int i = tid; i < 64*24; i += 256) {
            int row = i / 24, ch = i % 24;
            *(uint4*)&Ks[row*QS + ch*4] = *(const uint4*)(Kg + (size_t)(k0+row)*QKD + ch*8);
        }
        // V tile: 128 d-rows x 64 l (= 32 words = 8 uint4 chunks per row)
        for (int i = tid; i < 128*8; i += 256) {
            int d = i >> 3, ch = i & 7;
            *(uint4*)&Vs[d*VS + ch*4] = *(const uint4*)(Vg + (size_t)d*Ll + k0 + ch*8);
        }
        __syncthreads();

        // ---- S = Q K^T (warp-local m16 x n64), 12 k16-chunks ----
        float S[8][4];
#pragma unroll
        for (int j=0;j<8;j++)
#pragma unroll
            for (int t=0;t<4;t++) S[j][t]=0.f;

#pragma unroll
        for (int kk = 0; kk < 12; kk++) {
            unsigned a[4];
            a[0] = Qs[(m0+r  )*QS + kk*8 + c  ];
            a[1] = Qs[(m0+r+8)*QS + kk*8 + c  ];
            a[2] = Qs[(m0+r  )*QS + kk*8 + c+4];
            a[3] = Qs[(m0+r+8)*QS + kk*8 + c+4];
#pragma unroll
            for (int j = 0; j < 8; j++) {
                unsigned bfr[2];
                bfr[0] = Ks[(j*8+r)*QS + kk*8 + c  ];
                bfr[1] = Ks[(j*8+r)*QS + kk*8 + c+4];
                mma_h16(S[j], a, bfr);
            }
        }

        // ---- causal mask ----
        if (kt >= nkt - 2) {
            const int row0 = q0 + m0 + r;
            const int row1 = row0 + 8;
#pragma unroll
            for (int j = 0; j < 8; j++) {
                int col = k0 + j*8 + 2*c;
                if (col   > row0) S[j][0] = -1e30f;
                if (col+1 > row0) S[j][1] = -1e30f;
                if (col   > row1) S[j][2] = -1e30f;
                if (col+1 > row1) S[j][3] = -1e30f;
            }
        }

        // ---- online softmax ----
        float mx0 = -1e30f, mx1 = -1e30f;
#pragma unroll
        for (int j=0;j<8;j++) {
            mx0 = fmaxf(mx0, fmaxf(S[j][0], S[j][1]));
            mx1 = fmaxf(mx1, fmaxf(S[j][2], S[j][3]));
        }
        mx0 = fmaxf(mx0, __shfl_xor_sync(0xffffffffu, mx0, 1));
        mx0 = fmaxf(mx0, __shfl_xor_sync(0xffffffffu, mx0, 2));
        mx1 = fmaxf(mx1, __shfl_xor_sync(0xffffffffu, mx1, 1));
        mx1 = fmaxf(mx1, __shfl_xor_sync(0xffffffffu, mx1, 2));

        float mn0 = fmaxf(m_i[0], mx0), mn1 = fmaxf(m_i[1], mx1);
        float corr0 = __expf(m_i[0]-mn0), corr1 = __expf(m_i[1]-mn1);
        float rs0 = 0.f, rs1 = 0.f;
#pragma unroll
        for (int j=0;j<8;j++) {
            S[j][0] = __expf(S[j][0]-mn0); rs0 += S[j][0];
            S[j][1] = __expf(S[j][1]-mn0); rs0 += S[j][1];
            S[j][2] = __expf(S[j][2]-mn1); rs1 += S[j][2];
            S[j][3] = __expf(S[j][3]-mn1); rs1 += S[j][3];
        }
        rs0 += __shfl_xor_sync(0xffffffffu, rs0, 1);
        rs0 += __shfl_xor_sync(0xffffffffu, rs0, 2);
        rs1 += __shfl_xor_sync(0xffffffffu, rs1, 1);
        rs1 += __shfl_xor_sync(0xffffffffu, rs1, 2);
        l_i[0] = l_i[0]*corr0 + rs0;  m_i[0] = mn0;
        l_i[1] = l_i[1]*corr1 + rs1;  m_i[1] = mn1;

#pragma unroll
        for (int nb=0; nb<16; nb++) {
            O[nb][0]*=corr0; O[nb][1]*=corr0;
            O[nb][2]*=corr1; O[nb][3]*=corr1;
        }

        // ---- stage P (fp16) into own-warp rows ----
#pragma unroll
        for (int j=0;j<8;j++) {
            __half2 p0 = __floats2half2_rn(S[j][0], S[j][1]);
            __half2 p1 = __floats2half2_rn(S[j][2], S[j][3]);
            Ps[(m0+r  )*VS + j*4 + c] = *(unsigned*)&p0;
            Ps[(m0+r+8)*VS + j*4 + c] = *(unsigned*)&p1;
        }
        __syncwarp();

        // ---- O += P @ V  (4 k16-chunks over BK=64) ----
#pragma unroll
        for (int kk = 0; kk < 4; kk++) {
            unsigned a[4];
            a[0] = Ps[(m0+r  )*VS + kk*8 + c  ];
            a[1] = Ps[(m0+r+8)*VS + kk*8 + c  ];
            a[2] = Ps[(m0+r  )*VS + kk*8 + c+4];
            a[3] = Ps[(m0+r+8)*VS + kk*8 + c+4];
#pragma unroll
            for (int nb = 0; nb < 16; nb++) {
                unsigned bfr[2];
                bfr[0] = Vs[(nb*8+r)*VS + kk*8 + c  ];
                bfr[1] = Vs[(nb*8+r)*VS + kk*8 + c+4];
                mma_h16(O[nb], a, bfr);
            }
        }
    }

    // ---- epilogue: normalize and write fp16 ao (B*L, NH*DH) ----
    const int b = bh >> 4, h = bh & 15;
    const float inv0 = 1.0f / l_i[0];
    const float inv1 = 1.0f / l_i[1];
    const int l0 = q0 + m0 + r;
    __half* d0 = g_ao + ((size_t)(b*Ll + l0    ))*Dd + h*DHh;
    __half* d1 = g_ao + ((size_t)(b*Ll + l0 + 8))*Dd + h*DHh;
#pragma unroll
    for (int nb=0; nb<16; nb++) {
        *(__half2*)&d0[nb*8 + 2*c] = __floats2half2_rn(O[nb][0]*inv0, O[nb][1]*inv0);
        *(__half2*)&d1[nb*8 + 2*c] = __floats2half2_rn(O[nb][2]*inv1, O[nb][3]*inv1);
    }
}

// ---------------- launch ----------------
extern "C" void kernel_launch(void* const* d_in, const int* in_sizes, int n_in,
                              void* d_out, int out_size)
{
    const float* x     = (const float*)d_in[0];
    const float* W_DKV = (const float*)d_in[1];
    const float* W_UK  = (const float*)d_in[2];
    const float* W_UV  = (const float*)d_in[3];
    const float* W_DQ  = (const float*)d_in[4];
    const float* W_UQ  = (const float*)d_in[5];
    const float* W_QR  = (const float*)d_in[6];
    const float* W_KR  = (const float*)d_in[7];
    const float* W_O   = (const float*)d_in[8];
    const float* s_qk  = (const float*)d_in[9];
    float* out = (float*)d_out;

    __half *xh, *wdkvT, *wdqT, *wkrT, *wukT, *wuvT, *wuqT, *wqrT, *woT;
    __half *ckv, *cq, *kr, *kc, *vfl, *qc, *qr, *ao;
    cudaGetSymbolAddress((void**)&xh,    g_xh);
    cudaGetSymbolAddress((void**)&wdkvT, g_wdkvT);
    cudaGetSymbolAddress((void**)&wdqT,  g_wdqT);
    cudaGetSymbolAddress((void**)&wkrT,  g_wkrT);
    cudaGetSymbolAddress((void**)&wukT,  g_wukT);
    cudaGetSymbolAddress((void**)&wuvT,  g_wuvT);
    cudaGetSymbolAddress((void**)&wuqT,  g_wuqT);
    cudaGetSymbolAddress((void**)&wqrT,  g_wqrT);
    cudaGetSymbolAddress((void**)&woT,   g_woT);
    cudaGetSymbolAddress((void**)&ckv,   g_ckv);
    cudaGetSymbolAddress((void**)&cq,    g_cq);
    cudaGetSymbolAddress((void**)&kr,    g_kr);
    cudaGetSymbolAddress((void**)&kc,    g_kc);
    cudaGetSymbolAddress((void**)&vfl,   g_vfl);
    cudaGetSymbolAddress((void**)&qc,    g_qc);
    cudaGetSymbolAddress((void**)&qr,    g_qr);
    cudaGetSymbolAddress((void**)&ao,    g_ao);

    const int attn_smem = (128*QS + 64*QS + 128*VS + 128*VS) * (int)sizeof(unsigned);
    cudaFuncSetAttribute(attn_h16, cudaFuncAttributeMaxDynamicSharedMemorySize, attn_smem);

    dim3 thr(256);

    // ---- pre-pass: fp16 conversions / transposes ----
    cvt_x<<<(Mtok*Dd/4 + 255)/256, thr>>>(x, xh, Mtok*Dd/4);
    wtrans<<<dim3(DCc/32, Dd/32),  thr>>>(W_DKV, wdkvT, Dd, DCc);
    wtrans<<<dim3(DCc/32, Dd/32),  thr>>>(W_DQ,  wdqT,  Dd, DCc);
    wtrans<<<dim3(DHRr/32, Dd/32), thr>>>(W_KR,  wkrT,  Dd, DHRr);
    wtrans<<<dim3(Dd/32, DCc/32),  thr>>>(W_UK,  wukT,  DCc, Dd);
    wtrans<<<dim3(Dd/32, DCc/32),  thr>>>(W_UV,  wuvT,  DCc, Dd);
    wtrans<<<dim3(Dd/32, DCc/32),  thr>>>(W_UQ,  wuqT,  DCc, Dd);
    wtrans<<<dim3((NHh*DHRr)/32, DCc/32), thr>>>(W_QR, wqrT, DCc, NHh*DHRr);
    wtrans<<<dim3(Dd/32, Dd/32),   thr>>>(W_O,   woT,  Dd, Dd);

    // ---- projections (fp16 tensor cores) ----
    h16_gemm<false><<<dim3(DCc/128, Mtok/128), thr>>>(xh, wdkvT, ckv, Mtok, DCc, Dd);
    h16_gemm<false><<<dim3(DCc/128, Mtok/128), thr>>>(xh, wdqT,  cq,  Mtok, DCc, Dd);
    h16_gemm<false><<<dim3(1,        Mtok/128), thr>>>(xh, wkrT,  kr,  Mtok, DHRr, Dd);
    h16_gemm<false><<<dim3(Dd/128, Mtok/128), thr>>>(ckv, wukT, kc,  Mtok, Dd,  DCc);
    h16_gemm<false><<<dim3(Dd/128, Mtok/128), thr>>>(ckv, wuvT, vfl, Mtok, Dd,  DCc);
    h16_gemm<false><<<dim3(Dd/128, Mtok/128), thr>>>(cq,  wuqT, qc,  Mtok, Dd,  DCc);
    h16_gemm<false><<<dim3((NHh*DHRr)/128, Mtok/128), thr>>>(cq, wqrT, qr, Mtok, NHh*DHRr, DCc);

    // ---- V transpose + prep ----
    vtrans<<<dim3(Ll/64, Bb*NHh), thr>>>();
    prep2<<<dim3(Mtok, NHh), 192>>>(s_qk);

    // ---- attention ----
    attn_h16<<<dim3(Ll/128, Bb*NHh), thr, attn_smem>>>();

    // ---- output projection -> d_out (fp32 out) ----
    h16_gemm<true><<<dim3(Dd/128, Mtok/128), thr>>>(ao, woT, out, Mtok, Dd, Dd);
}

// round 6
// speedup vs baseline: 8.1788x; 1.4394x over previous
#include <cuda_runtime.h>
#include <cuda_fp16.h>
#include <math.h>

// ---------------- problem constants ----------------
#define Bb 4
#define Ll 2048
#define Dd 2048
#define NHh 16
#define DHh 128
#define DHRr 64
#define DCc 1024
#define Mtok (Bb*Ll)            // 8192
#define QKD 192                 // DH + DHR

// ---------------- device scratch (static, allocation-free) ----------------
__device__ __half g_xh   [(size_t)Mtok*Dd];
__device__ __half g_wdkvT[(size_t)DCc*Dd];
__device__ __half g_wdqT [(size_t)DCc*Dd];
__device__ __half g_wkrT [(size_t)DHRr*Dd];
__device__ __half g_wukT [(size_t)Dd*DCc];
__device__ __half g_wuvT [(size_t)Dd*DCc];
__device__ __half g_wuqT [(size_t)Dd*DCc];
__device__ __half g_wqrT [(size_t)(NHh*DHRr)*DCc];
__device__ __half g_woT  [(size_t)Dd*Dd];
__device__ __half g_ckv  [(size_t)Mtok*DCc];
__device__ __half g_cq   [(size_t)Mtok*DCc];
__device__ __half g_kr   [(size_t)Mtok*DHRr];
__device__ __half g_kc   [(size_t)Mtok*Dd];
__device__ __half g_vfl  [(size_t)Mtok*Dd];
__device__ __half g_qc   [(size_t)Mtok*Dd];
__device__ __half g_qr   [(size_t)Mtok*(NHh*DHRr)];
__device__ __half g_q    [(size_t)Bb*NHh*Ll*QKD];
__device__ __half g_k    [(size_t)Bb*NHh*Ll*QKD];
__device__ __half g_vt   [(size_t)Bb*NHh*DHh*Ll];   // [bh][d][l]
__device__ __half g_ao   [(size_t)Mtok*Dd];

// ---------------- asm helpers ----------------
__device__ __forceinline__ void mma_h16(float* d, const unsigned* a, const unsigned* b) {
    asm volatile(
        "mma.sync.aligned.m16n8k16.row.col.f32.f16.f16.f32 "
        "{%0,%1,%2,%3}, {%4,%5,%6,%7}, {%8,%9}, {%0,%1,%2,%3};"
        : "+f"(d[0]), "+f"(d[1]), "+f"(d[2]), "+f"(d[3])
        : "r"(a[0]), "r"(a[1]), "r"(a[2]), "r"(a[3]), "r"(b[0]), "r"(b[1]));
}

__device__ __forceinline__ unsigned smem_u32(const void* p) {
    return (unsigned)__cvta_generic_to_shared(p);
}

__device__ __forceinline__ void ldsm4(unsigned* r, unsigned addr) {
    asm volatile("ldmatrix.sync.aligned.m8n8.x4.shared.b16 {%0,%1,%2,%3}, [%4];"
        : "=r"(r[0]), "=r"(r[1]), "=r"(r[2]), "=r"(r[3]) : "r"(addr));
}

__device__ __forceinline__ void cp16(unsigned dst, const void* src) {
    asm volatile("cp.async.cg.shared.global [%0], [%1], 16;" :: "r"(dst), "l"(src));
}
#define CP_COMMIT() asm volatile("cp.async.commit_group;")
#define CP_WAIT(N)  asm volatile("cp.async.wait_group %0;" :: "n"(N))

// ---------------- pre-pass: x fp32 -> fp16 ----------------
__global__ void __launch_bounds__(256) cvt_x(const float* __restrict__ x, __half* __restrict__ xh, int n4)
{
    int i = blockIdx.x*256 + threadIdx.x;
    if (i < n4) {
        float4 v = ((const float4*)x)[i];
        __half2* o = (__half2*)xh;
        o[2*i]   = __floats2half2_rn(v.x, v.y);
        o[2*i+1] = __floats2half2_rn(v.z, v.w);
    }
}

// ---------------- pre-pass: W [K][N] fp32 -> Wt [N][K] fp16 ----------------
__global__ void __launch_bounds__(256) wtrans(const float* __restrict__ W, __half* __restrict__ Wt,
                                              int K, int N)
{
    __shared__ __half t[32][33];
    const int n0 = blockIdx.x*32, k0 = blockIdx.y*32;
    const int tx = threadIdx.x & 31, ty = threadIdx.x >> 5;   // 32x8
#pragma unroll
    for (int i=0;i<4;i++)
        t[ty+i*8][tx] = __float2half(W[(size_t)(k0+ty+i*8)*N + n0+tx]);
    __syncthreads();
#pragma unroll
    for (int i=0;i<4;i++)
        Wt[(size_t)(n0+ty+i*8)*K + k0+tx] = t[tx][ty+i*8];
}

// ---------------- fp16 tensor-core GEMM: C[M][N] = A[M][K] * Bt[N][K]^T ----
// 128x128x32 CTA tile, 8 warps (2x4), 64x32 warp tile, m16n8k16 atoms.
// ldmatrix fragment loads; 3-stage cp.async smem pipeline.
#define HS 20                       // words per k32 row (conflict-free for ldsm)
#define GST (128*HS)                // words per stage per operand (2560)
template<bool OUTF32>
__global__ void __launch_bounds__(256)
h16_gemm(const __half* __restrict__ A, const __half* __restrict__ Bt,
         void* __restrict__ Cv, int M, int N, int K)
{
    extern __shared__ unsigned gsm[];
    const unsigned sA = smem_u32(gsm);
    const unsigned sB = sA + 3*GST*4;

    const int tid  = threadIdx.x;
    const int lane = tid & 31;
    const int warp = tid >> 5;
    const int wm = warp >> 2, wn = warp & 3;
    const int ln15 = lane & 15;
    const int hi16 = (lane >> 4) * 16;

    const __half* Ag = A  + (size_t)blockIdx.y * 128 * K;
    const __half* Bg = Bt + (size_t)blockIdx.x * 128 * K;
    const int nrem = N - blockIdx.x*128;

    const int arow  = tid >> 2;          // 0..63
    const int arow2 = arow + 64;
    const int ach   = tid & 3;
    const int brow  = (arow  < nrem) ? arow  : (nrem-1);
    const int brow2 = (arow2 < nrem) ? arow2 : (nrem-1);

    // per-thread smem store word offsets
    const unsigned stA0 = (arow *HS + ach*4)*4;
    const unsigned stA1 = (arow2*HS + ach*4)*4;

    // fragment base byte offsets (within a stage)
    unsigned afo[4], bfo[2];
#pragma unroll
    for (int ma=0; ma<4; ma++) afo[ma] = ((wm*64 + ma*16 + ln15)*HS)*4 + hi16;
#pragma unroll
    for (int nb=0; nb<2; nb++) bfo[nb] = ((wn*32 + nb*16 + ln15)*HS)*4 + hi16;

    float acc[4][4][4];
#pragma unroll
    for (int i=0;i<4;i++)
#pragma unroll
        for (int j=0;j<4;j++)
#pragma unroll
            for (int t=0;t<4;t++) acc[i][j][t]=0.f;

    const int nk = K/32;

    // prologue: stages 0,1
#pragma unroll
    for (int s=0; s<2; s++) {
        const int k0 = s*32;
        cp16(sA + s*GST*4 + stA0, Ag + (size_t)arow *K + k0 + ach*8);
        cp16(sA + s*GST*4 + stA1, Ag + (size_t)arow2*K + k0 + ach*8);
        cp16(sB + s*GST*4 + stA0, Bg + (size_t)brow *K + k0 + ach*8);
        cp16(sB + s*GST*4 + stA1, Bg + (size_t)brow2*K + k0 + ach*8);
        CP_COMMIT();
    }

    for (int kt=0; kt<nk; kt++) {
        CP_WAIT(1);
        __syncthreads();

        const int kn = kt+2;
        if (kn < nk) {
            const int sn = kn % 3;
            const int k0 = kn*32;
            cp16(sA + sn*GST*4 + stA0, Ag + (size_t)arow *K + k0 + ach*8);
            cp16(sA + sn*GST*4 + stA1, Ag + (size_t)arow2*K + k0 + ach*8);
            cp16(sB + sn*GST*4 + stA0, Bg + (size_t)brow *K + k0 + ach*8);
            cp16(sB + sn*GST*4 + stA1, Bg + (size_t)brow2*K + k0 + ach*8);
        }
        CP_COMMIT();

        const unsigned aS = sA + (kt%3)*GST*4;
        const unsigned bS = sB + (kt%3)*GST*4;
#pragma unroll
        for (int kc8 = 0; kc8 < 16; kc8 += 8) {    // two k16 chunks
            unsigned af[4][4];
#pragma unroll
            for (int ma=0;ma<4;ma++)
                ldsm4(af[ma], aS + afo[ma] + kc8*4);
#pragma unroll
            for (int nb=0;nb<2;nb++) {
                unsigned bq[4];
                ldsm4(bq, bS + bfo[nb] + kc8*4);
                unsigned b0[2] = {bq[0], bq[2]};
                unsigned b1[2] = {bq[1], bq[3]};
#pragma unroll
                for (int ma=0;ma<4;ma++) {
                    mma_h16(acc[ma][nb*2  ], af[ma], b0);
                    mma_h16(acc[ma][nb*2+1], af[ma], b1);
                }
            }
        }
    }

    const int r = lane >> 2, c = lane & 3;
#pragma unroll
    for (int ma=0;ma<4;ma++) {
        int m = blockIdx.y*128 + wm*64 + ma*16 + r;
#pragma unroll
        for (int na=0;na<4;na++) {
            int n = blockIdx.x*128 + wn*32 + na*8 + 2*c;
            if (n < N) {
                if (OUTF32) {
                    float* C = (float*)Cv;
                    *(float2*)&C[(size_t)m*N + n]     = make_float2(acc[ma][na][0], acc[ma][na][1]);
                    *(float2*)&C[(size_t)(m+8)*N + n] = make_float2(acc[ma][na][2], acc[ma][na][3]);
                } else {
                    __half* C = (__half*)Cv;
                    *(__half2*)&C[(size_t)m*N + n]     = __floats2half2_rn(acc[ma][na][0], acc[ma][na][1]);
                    *(__half2*)&C[(size_t)(m+8)*N + n] = __floats2half2_rn(acc[ma][na][2], acc[ma][na][3]);
                }
            }
        }
    }
}

// ---------------- V transpose: g_vfl [bl][h*128+d] -> g_vt [bh][d][l] ------
__global__ void __launch_bounds__(256) vtrans()
{
    __shared__ __half t[64][DHh+8];
    const int bh = blockIdx.y, b = bh >> 4, h = bh & 15;
    const int l0 = blockIdx.x * 64;
    const int tid = threadIdx.x;

    for (int i = tid; i < 64*16; i += 256) {
        int l = i >> 4, ch = i & 15;
        *(uint4*)&t[l][ch*8] =
            *(const uint4*)(g_vfl + ((size_t)(b*Ll + l0 + l))*Dd + h*DHh + ch*8);
    }
    __syncthreads();
    for (int i = tid; i < 128*8; i += 256) {
        int d = i >> 3, ch = i & 7;
        __half2 p[4];
#pragma unroll
        for (int u=0;u<4;u++) {
            int l = ch*8 + u*2;
            p[u] = __halves2half2(t[l][d], t[l+1][d]);
        }
        *(uint4*)(g_vt + (size_t)bh*DHh*Ll + (size_t)d*Ll + l0 + ch*8) = *(uint4*)p;
    }
}

// ---------------- prep: RoPE + concat + normalize + scale ------------------
__global__ void __launch_bounds__(192) prep2(const float* __restrict__ s_qk_ptr)
{
    const int bl = blockIdx.x, h = blockIdx.y;
    const int b = bl >> 11, l = bl & 2047;
    const int t = threadIdx.x;

    __shared__ float red[2][6];
    const float s_qk = *s_qk_ptr;

    float kv, qv;
    if (t < 128) {
        kv = __half2float(g_kc[(size_t)bl*Dd + h*DHh + t]);
        qv = __half2float(g_qc[(size_t)bl*Dd + h*DHh + t]);
    } else {
        int j = t - 128, jj = j & 31;
        float inv = powf(10000.0f, -(float)jj/32.0f);
        float ang = (float)l * inv;
        float csv = cosf(ang), snv = sinf(ang);
        {
            float v  = __half2float(g_kr[(size_t)bl*DHRr + j]);
            float vo = __half2float(g_kr[(size_t)bl*DHRr + (j<32 ? j+32 : j-32)]);
            float rot = (j<32) ? -vo : vo;
            kv = v*csv + rot*snv;
        }
        {
            const __half* qrp = g_qr + (size_t)bl*(NHh*DHRr) + h*DHRr;
            float v  = __half2float(qrp[j]);
            float vo = __half2float(qrp[(j<32 ? j+32 : j-32)]);
            float rot = (j<32) ? -vo : vo;
            qv = v*csv + rot*snv;
        }
    }

    float ks = kv*kv, qs = qv*qv;
#pragma unroll
    for (int o=16;o>0;o>>=1) {
        ks += __shfl_xor_sync(0xffffffffu, ks, o);
        qs += __shfl_xor_sync(0xffffffffu, qs, o);
    }
    const int w = t >> 5;
    if ((t & 31) == 0) { red[0][w] = ks; red[1][w] = qs; }
    __syncthreads();
    float ksum = red[0][0]+red[0][1]+red[0][2]+red[0][3]+red[0][4]+red[0][5];
    float qsum = red[1][0]+red[1][1]+red[1][2]+red[1][3]+red[1][4]+red[1][5];
    float invk = 1.0f / fmaxf(sqrtf(ksum), 1e-12f);
    float invq = s_qk / fmaxf(sqrtf(qsum), 1e-12f);

    size_t off = ((size_t)(b*NHh + h)*Ll + l)*QKD + t;
    g_k[off] = __float2half(kv*invk);
    g_q[off] = __float2half(qv*invq);
}

// ---------------- fp16 flash attention (causal, BQ=128, BK=64) -------------
// 8 warps; warp w owns rows [w*16, w*16+16); warp-local softmax.
// ldmatrix fragments; 2-stage cp.async K/V double buffer.
#define QS 100
#define VS 36
#define KST (64*QS)     // words per K stage (6400)
#define VST (128*VS)    // words per V stage (4608)
__global__ void __launch_bounds__(256, 1) attn_h16()
{
    extern __shared__ unsigned smu[];
    unsigned* Qs = smu;                        // [128][100]
    const unsigned sQ = smem_u32(Qs);
    const unsigned sK = sQ + 128*QS*4;         // 2 stages [64][100]
    const unsigned sV = sK + 2*KST*4;          // 2 stages [128][36]
    const unsigned sP = sV + 2*VST*4;          // [128][36]
    unsigned* Ps = smu + (128*QS + 2*KST + 2*VST);

    const int qt = (gridDim.x - 1) - blockIdx.x;   // heavy blocks first
    const int bh = blockIdx.y;
    const int q0 = qt * 128;
    const __half* Qg = g_q  + (size_t)bh*Ll*QKD + (size_t)q0*QKD;
    const __half* Kg = g_k  + (size_t)bh*Ll*QKD;
    const __half* Vg = g_vt + (size_t)bh*DHh*Ll;

    const int tid  = threadIdx.x;
    const int lane = tid & 31;
    const int warp = tid >> 5;
    const int r = lane >> 2, c = lane & 3;
    const int ln15 = lane & 15;
    const int hi16 = (lane >> 4) * 16;
    const int m0 = warp * 16;

    // load Q tile (once)
    for (int i = tid; i < 128*24; i += 256) {
        int row = i / 24, ch = i % 24;
        *(uint4*)&Qs[row*QS + ch*4] = *(const uint4*)(Qg + (size_t)row*QKD + ch*8);
    }

    // fragment base addresses
    const unsigned qbase = sQ + ((m0 + ln15)*QS)*4 + hi16;
    const unsigned pbase = sP + ((m0 + ln15)*VS)*4 + hi16;

    float O[16][4];
#pragma unroll
    for (int nb=0; nb<16; nb++)
#pragma unroll
        for (int t=0; t<4; t++) O[nb][t] = 0.f;
    float m_i[2] = {-1e30f, -1e30f};
    float l_i[2] = {0.f, 0.f};

    const int nkt = 2*(qt+1);

    // prologue: K/V tile 0 -> stage 0
    {
        for (int i = tid; i < 64*24; i += 256) {
            int row = i / 24, ch = i % 24;
            cp16(sK + (row*QS + ch*4)*4, Kg + (size_t)row*QKD + ch*8);
        }
        for (int i = tid; i < 128*8; i += 256) {
            int d = i >> 3, ch = i & 7;
            cp16(sV + (d*VS + ch*4)*4, Vg + (size_t)d*Ll + ch*8);
        }
        CP_COMMIT();
    }

    for (int kt = 0; kt < nkt; kt++) {
        // issue next tile into the other stage
        if (kt+1 < nkt) {
            const int k0n = (kt+1)*64;
            const unsigned kS = sK + ((kt+1)&1)*KST*4;
            const unsigned vS = sV + ((kt+1)&1)*VST*4;
            for (int i = tid; i < 64*24; i += 256) {
                int row = i / 24, ch = i % 24;
                cp16(kS + (row*QS + ch*4)*4, Kg + (size_t)(k0n+row)*QKD + ch*8);
            }
            for (int i = tid; i < 128*8; i += 256) {
                int d = i >> 3, ch = i & 7;
                cp16(vS + (d*VS + ch*4)*4, Vg + (size_t)d*Ll + k0n + ch*8);
            }
        }
        CP_COMMIT();
        CP_WAIT(1);
        __syncthreads();

        const unsigned kS = sK + (kt&1)*KST*4;
        const unsigned vS = sV + (kt&1)*VST*4;
        const int k0 = kt*64;

        // ---- S = Q K^T (warp-local m16 x n64), 12 k16-chunks ----
        float S[8][4];
#pragma unroll
        for (int j=0;j<8;j++)
#pragma unroll
            for (int t=0;t<4;t++) S[j][t]=0.f;

#pragma unroll
        for (int kk = 0; kk < 12; kk++) {
            unsigned a[4];
            ldsm4(a, qbase + kk*32);
#pragma unroll
            for (int p = 0; p < 4; p++) {
                unsigned bq[4];
                ldsm4(bq, kS + ((p*16 + ln15)*QS)*4 + hi16 + kk*32);
                unsigned b0[2] = {bq[0], bq[2]};
                unsigned b1[2] = {bq[1], bq[3]};
                mma_h16(S[p*2  ], a, b0);
                mma_h16(S[p*2+1], a, b1);
            }
        }

        // ---- causal mask ----
        if (kt >= nkt - 2) {
            const int row0 = q0 + m0 + r;
            const int row1 = row0 + 8;
#pragma unroll
            for (int j = 0; j < 8; j++) {
                int col = k0 + j*8 + 2*c;
                if (col   > row0) S[j][0] = -1e30f;
                if (col+1 > row0) S[j][1] = -1e30f;
                if (col   > row1) S[j][2] = -1e30f;
                if (col+1 > row1) S[j][3] = -1e30f;
            }
        }

        // ---- online softmax ----
        float mx0 = -1e30f, mx1 = -1e30f;
#pragma unroll
        for (int j=0;j<8;j++) {
            mx0 = fmaxf(mx0, fmaxf(S[j][0], S[j][1]));
            mx1 = fmaxf(mx1, fmaxf(S[j][2], S[j][3]));
        }
        mx0 = fmaxf(mx0, __shfl_xor_sync(0xffffffffu, mx0, 1));
        mx0 = fmaxf(mx0, __shfl_xor_sync(0xffffffffu, mx0, 2));
        mx1 = fmaxf(mx1, __shfl_xor_sync(0xffffffffu, mx1, 1));
        mx1 = fmaxf(mx1, __shfl_xor_sync(0xffffffffu, mx1, 2));

        float mn0 = fmaxf(m_i[0], mx0), mn1 = fmaxf(m_i[1], mx1);
        float corr0 = __expf(m_i[0]-mn0), corr1 = __expf(m_i[1]-mn1);
        float rs0 = 0.f, rs1 = 0.f;
#pragma unroll
        for (int j=0;j<8;j++) {
            S[j][0] = __expf(S[j][0]-mn0); rs0 += S[j][0];
            S[j][1] = __expf(S[j][1]-mn0); rs0 += S[j][1];
            S[j][2] = __expf(S[j][2]-mn1); rs1 += S[j][2];
            S[j][3] = __expf(S[j][3]-mn1); rs1 += S[j][3];
        }
        rs0 += __shfl_xor_sync(0xffffffffu, rs0, 1);
        rs0 += __shfl_xor_sync(0xffffffffu, rs0, 2);
        rs1 += __shfl_xor_sync(0xffffffffu, rs1, 1);
        rs1 += __shfl_xor_sync(0xffffffffu, rs1, 2);
        l_i[0] = l_i[0]*corr0 + rs0;  m_i[0] = mn0;
        l_i[1] = l_i[1]*corr1 + rs1;  m_i[1] = mn1;

#pragma unroll
        for (int nb=0; nb<16; nb++) {
            O[nb][0]*=corr0; O[nb][1]*=corr0;
            O[nb][2]*=corr1; O[nb][3]*=corr1;
        }

        // ---- stage P (fp16) into own-warp rows ----
#pragma unroll
        for (int j=0;j<8;j++) {
            __half2 p0 = __floats2half2_rn(S[j][0], S[j][1]);
            __half2 p1 = __floats2half2_rn(S[j][2], S[j][3]);
            Ps[(m0+r  )*VS + j*4 + c] = *(unsigned*)&p0;
            Ps[(m0+r+8)*VS + j*4 + c] = *(unsigned*)&p1;
        }
        __syncwarp();

        // ---- O += P @ V  (4 k16-chunks over BK=64) ----
#pragma unroll
        for (int kk = 0; kk < 4; kk++) {
            unsigned a[4];
            ldsm4(a, pbase + kk*32);
#pragma unroll
            for (int p = 0; p < 8; p++) {
                unsigned bq[4];
                ldsm4(bq, vS + ((p*16 + ln15)*VS)*4 + hi16 + kk*32);
                unsigned b0[2] = {bq[0], bq[2]};
                unsigned b1[2] = {bq[1], bq[3]};
                mma_h16(O[p*2  ], a, b0);
                mma_h16(O[p*2+1], a, b1);
            }
        }
        __syncthreads();   // all warps done with this stage before it is reloaded
    }

    // ---- epilogue: normalize and write fp16 ao (B*L, NH*DH) ----
    const int b = bh >> 4, h = bh & 15;
    const float inv0 = 1.0f / l_i[0];
    const float inv1 = 1.0f / l_i[1];
    const int l0 = q0 + m0 + r;
    __half* d0 = g_ao + ((size_t)(b*Ll + l0    ))*Dd + h*DHh;
    __half* d1 = g_ao + ((size_t)(b*Ll + l0 + 8))*Dd + h*DHh;
#pragma unroll
    for (int nb=0; nb<16; nb++) {
        *(__half2*)&d0[nb*8 + 2*c] = __floats2half2_rn(O[nb][0]*inv0, O[nb][1]*inv0);
        *(__half2*)&d1[nb*8 + 2*c] = __floats2half2_rn(O[nb][2]*inv1, O[nb][3]*inv1);
    }
}

// ---------------- launch ----------------
extern "C" void kernel_launch(void* const* d_in, const int* in_sizes, int n_in,
                              void* d_out, int out_size)
{
    const float* x     = (const float*)d_in[0];
    const float* W_DKV = (const float*)d_in[1];
    const float* W_UK  = (const float*)d_in[2];
    const float* W_UV  = (const float*)d_in[3];
    const float* W_DQ  = (const float*)d_in[4];
    const float* W_UQ  = (const float*)d_in[5];
    const float* W_QR  = (const float*)d_in[6];
    const float* W_KR  = (const float*)d_in[7];
    const float* W_O   = (const float*)d_in[8];
    const float* s_qk  = (const float*)d_in[9];
    float* out = (float*)d_out;

    __half *xh, *wdkvT, *wdqT, *wkrT, *wukT, *wuvT, *wuqT, *wqrT, *woT;
    __half *ckv, *cq, *kr, *kc, *vfl, *qc, *qr, *ao;
    cudaGetSymbolAddress((void**)&xh,    g_xh);
    cudaGetSymbolAddress((void**)&wdkvT, g_wdkvT);
    cudaGetSymbolAddress((void**)&wdqT,  g_wdqT);
    cudaGetSymbolAddress((void**)&wkrT,  g_wkrT);
    cudaGetSymbolAddress((void**)&wukT,  g_wukT);
    cudaGetSymbolAddress((void**)&wuvT,  g_wuvT);
    cudaGetSymbolAddress((void**)&wuqT,  g_wuqT);
    cudaGetSymbolAddress((void**)&wqrT,  g_wqrT);
    cudaGetSymbolAddress((void**)&woT,   g_woT);
    cudaGetSymbolAddress((void**)&ckv,   g_ckv);
    cudaGetSymbolAddress((void**)&cq,    g_cq);
    cudaGetSymbolAddress((void**)&kr,    g_kr);
    cudaGetSymbolAddress((void**)&kc,    g_kc);
    cudaGetSymbolAddress((void**)&vfl,   g_vfl);
    cudaGetSymbolAddress((void**)&qc,    g_qc);
    cudaGetSymbolAddress((void**)&qr,    g_qr);
    cudaGetSymbolAddress((void**)&ao,    g_ao);

    const int gemm_smem = 6*GST*4;                                   // 61440
    cudaFuncSetAttribute(h16_gemm<false>, cudaFuncAttributeMaxDynamicSharedMemorySize, gemm_smem);
    cudaFuncSetAttribute(h16_gemm<true>,  cudaFuncAttributeMaxDynamicSharedMemorySize, gemm_smem);
    const int attn_smem = (128*QS + 2*KST + 2*VST + 128*VS) * 4;     // 157696
    cudaFuncSetAttribute(attn_h16, cudaFuncAttributeMaxDynamicSharedMemorySize, attn_smem);

    dim3 thr(256);

    // ---- pre-pass: fp16 conversions / transposes ----
    cvt_x<<<(Mtok*Dd/4 + 255)/256, thr>>>(x, xh, Mtok*Dd/4);
    wtrans<<<dim3(DCc/32, Dd/32),  thr>>>(W_DKV, wdkvT, Dd, DCc);
    wtrans<<<dim3(DCc/32, Dd/32),  thr>>>(W_DQ,  wdqT,  Dd, DCc);
    wtrans<<<dim3(DHRr/32, Dd/32), thr>>>(W_KR,  wkrT,  Dd, DHRr);
    wtrans<<<dim3(Dd/32, DCc/32),  thr>>>(W_UK,  wukT,  DCc, Dd);
    wtrans<<<dim3(Dd/32, DCc/32),  thr>>>(W_UV,  wuvT,  DCc, Dd);
    wtrans<<<dim3(Dd/32, DCc/32),  thr>>>(W_UQ,  wuqT,  DCc, Dd);
    wtrans<<<dim3((NHh*DHRr)/32, DCc/32), thr>>>(W_QR, wqrT, DCc, NHh*DHRr);
    wtrans<<<dim3(Dd/32, Dd/32),   thr>>>(W_O,   woT,  Dd, Dd);

    // ---- projections (fp16 tensor cores) ----
    h16_gemm<false><<<dim3(DCc/128, Mtok/128), thr, gemm_smem>>>(xh, wdkvT, ckv, Mtok, DCc, Dd);
    h16_gemm<false><<<dim3(DCc/128, Mtok/128), thr, gemm_smem>>>(xh, wdqT,  cq,  Mtok, DCc, Dd);
    h16_gemm<false><<<dim3(1,        Mtok/128), thr, gemm_smem>>>(xh, wkrT,  kr,  Mtok, DHRr, Dd);
    h16_gemm<false><<<dim3(Dd/128, Mtok/128), thr, gemm_smem>>>(ckv, wukT, kc,  Mtok, Dd,  DCc);
    h16_gemm<false><<<dim3(Dd/128, Mtok/128), thr, gemm_smem>>>(ckv, wuvT, vfl, Mtok, Dd,  DCc);
    h16_gemm<false><<<dim3(Dd/128, Mtok/128), thr, gemm_smem>>>(cq,  wuqT, qc,  Mtok, Dd,  DCc);
    h16_gemm<false><<<dim3((NHh*DHRr)/128, Mtok/128), thr, gemm_smem>>>(cq, wqrT, qr, Mtok, NHh*DHRr, DCc);

    // ---- V transpose + prep ----
    vtrans<<<dim3(Ll/64, Bb*NHh), thr>>>();
    prep2<<<dim3(Mtok, NHh), 192>>>(s_qk);

    // ---- attention ----
    attn_h16<<<dim3(Ll/128, Bb*NHh), thr, attn_smem>>>();

    // ---- output projection -> d_out (fp32 out) ----
    h16_gemm<true><<<dim3(Dd/128, Mtok/128), thr, gemm_smem>>>(ao, woT, out, Mtok, Dd, Dd);
}

// round 7
// speedup vs baseline: 8.9157x; 1.0901x over previous
#include <cuda_runtime.h>
#include <cuda_fp16.h>
#include <math.h>

// ---------------- problem constants ----------------
#define Bb 4
#define Ll 2048
#define Dd 2048
#define NHh 16
#define DHh 128
#define DHRr 64
#define DCc 1024
#define Mtok (Bb*Ll)            // 8192
#define QKD 192                 // DH + DHR
#define N1 (DCc + DCc + DHRr)   // 2112 : [ckv | cq | kr]
#define N2 (Dd + Dd)            // 4096 : [kc | vfl]
#define N3 (Dd + NHh*DHRr)      // 3072 : [qc | qr]

// ---------------- device scratch (static, allocation-free) ----------------
__device__ __half g_xh  [(size_t)Mtok*Dd];
__device__ __half g_w1t [(size_t)N1*Dd];     // [2112][2048]
__device__ __half g_w2t [(size_t)N2*DCc];    // [4096][1024]
__device__ __half g_w3t [(size_t)N3*DCc];    // [3072][1024]
__device__ __half g_woT [(size_t)Dd*Dd];
__device__ __half g_c1  [(size_t)Mtok*N1];   // ckv | cq | kr
__device__ __half g_c2  [(size_t)Mtok*N2];   // kc | vfl
__device__ __half g_c3  [(size_t)Mtok*N3];   // qc | qr
__device__ __half g_q   [(size_t)Bb*NHh*Ll*QKD];
__device__ __half g_k   [(size_t)Bb*NHh*Ll*QKD];
__device__ __half g_vt  [(size_t)Bb*NHh*DHh*Ll];   // [bh][d][l]
__device__ __half g_ao  [(size_t)Mtok*Dd];

// ---------------- asm helpers ----------------
__device__ __forceinline__ void mma_h16(float* d, const unsigned* a, const unsigned* b) {
    asm volatile(
        "mma.sync.aligned.m16n8k16.row.col.f32.f16.f16.f32 "
        "{%0,%1,%2,%3}, {%4,%5,%6,%7}, {%8,%9}, {%0,%1,%2,%3};"
        : "+f"(d[0]), "+f"(d[1]), "+f"(d[2]), "+f"(d[3])
        : "r"(a[0]), "r"(a[1]), "r"(a[2]), "r"(a[3]), "r"(b[0]), "r"(b[1]));
}

__device__ __forceinline__ unsigned smem_u32(const void* p) {
    return (unsigned)__cvta_generic_to_shared(p);
}

__device__ __forceinline__ void ldsm4(unsigned* r, unsigned addr) {
    asm volatile("ldmatrix.sync.aligned.m8n8.x4.shared.b16 {%0,%1,%2,%3}, [%4];"
        : "=r"(r[0]), "=r"(r[1]), "=r"(r[2]), "=r"(r[3]) : "r"(addr));
}

__device__ __forceinline__ void cp16(unsigned dst, const void* src) {
    asm volatile("cp.async.cg.shared.global [%0], [%1], 16;" :: "r"(dst), "l"(src));
}
#define CP_COMMIT() asm volatile("cp.async.commit_group;")
#define CP_WAIT(N)  asm volatile("cp.async.wait_group %0;" :: "n"(N))

// ---------------- pre-pass: x fp32 -> fp16 ----------------
__global__ void __launch_bounds__(256) cvt_x(const float* __restrict__ x, __half* __restrict__ xh, int n4)
{
    int i = blockIdx.x*256 + threadIdx.x;
    if (i < n4) {
        float4 v = ((const float4*)x)[i];
        __half2* o = (__half2*)xh;
        o[2*i]   = __floats2half2_rn(v.x, v.y);
        o[2*i+1] = __floats2half2_rn(v.z, v.w);
    }
}

// ---------------- pre-pass: W [K][N] fp32 -> Wt [N][K] fp16 ----------------
__global__ void __launch_bounds__(256) wtrans(const float* __restrict__ W, __half* __restrict__ Wt,
                                              int K, int N)
{
    __shared__ __half t[32][33];
    const int n0 = blockIdx.x*32, k0 = blockIdx.y*32;
    const int tx = threadIdx.x & 31, ty = threadIdx.x >> 5;   // 32x8
#pragma unroll
    for (int i=0;i<4;i++)
        t[ty+i*8][tx] = __float2half(W[(size_t)(k0+ty+i*8)*N + n0+tx]);
    __syncthreads();
#pragma unroll
    for (int i=0;i<4;i++)
        Wt[(size_t)(n0+ty+i*8)*K + k0+tx] = t[tx][ty+i*8];
}

// ---------------- fp16 tensor-core GEMM: C[M][N] = A * Bt^T ----------------
// A rows stride lda, C rows stride ldc. 128x128x32 CTA, 8 warps, ldmatrix,
// 3-stage cp.async pipeline, 2 CTAs/SM.
#define HS 20                       // words per k32 row (stride w/ pad)
#define GST (128*HS)                // words per stage per operand
template<bool OUTF32>
__global__ void __launch_bounds__(256, 2)
h16_gemm(const __half* __restrict__ A, const __half* __restrict__ Bt,
         void* __restrict__ Cv, int N, int K, int lda, int ldc)
{
    extern __shared__ unsigned gsm[];
    const unsigned sA = smem_u32(gsm);
    const unsigned sB = sA + 3*GST*4;

    const int tid  = threadIdx.x;
    const int lane = tid & 31;
    const int warp = tid >> 5;
    const int wm = warp >> 2, wn = warp & 3;
    const int ln15 = lane & 15;
    const int hi16 = (lane >> 4) * 16;

    const __half* Ag = A  + (size_t)blockIdx.y * 128 * lda;
    const __half* Bg = Bt + (size_t)blockIdx.x * 128 * K;
    const int nrem = N - blockIdx.x*128;

    const int arow  = tid >> 2;          // 0..63
    const int arow2 = arow + 64;
    const int ach   = tid & 3;
    const int brow  = (arow  < nrem) ? arow  : (nrem-1);
    const int brow2 = (arow2 < nrem) ? arow2 : (nrem-1);

    const unsigned stA0 = (arow *HS + ach*4)*4;
    const unsigned stA1 = (arow2*HS + ach*4)*4;

    unsigned afo[4], bfo[2];
#pragma unroll
    for (int ma=0; ma<4; ma++) afo[ma] = ((wm*64 + ma*16 + ln15)*HS)*4 + hi16;
#pragma unroll
    for (int nb=0; nb<2; nb++) bfo[nb] = ((wn*32 + nb*16 + ln15)*HS)*4 + hi16;

    float acc[4][4][4];
#pragma unroll
    for (int i=0;i<4;i++)
#pragma unroll
        for (int j=0;j<4;j++)
#pragma unroll
            for (int t=0;t<4;t++) acc[i][j][t]=0.f;

    const int nk = K/32;

#pragma unroll
    for (int s=0; s<2; s++) {
        const int k0 = s*32;
        cp16(sA + s*GST*4 + stA0, Ag + (size_t)arow *lda + k0 + ach*8);
        cp16(sA + s*GST*4 + stA1, Ag + (size_t)arow2*lda + k0 + ach*8);
        cp16(sB + s*GST*4 + stA0, Bg + (size_t)brow *K + k0 + ach*8);
        cp16(sB + s*GST*4 + stA1, Bg + (size_t)brow2*K + k0 + ach*8);
        CP_COMMIT();
    }

    for (int kt=0; kt<nk; kt++) {
        CP_WAIT(1);
        __syncthreads();

        const int kn = kt+2;
        if (kn < nk) {
            const int sn = kn % 3;
            const int k0 = kn*32;
            cp16(sA + sn*GST*4 + stA0, Ag + (size_t)arow *lda + k0 + ach*8);
            cp16(sA + sn*GST*4 + stA1, Ag + (size_t)arow2*lda + k0 + ach*8);
            cp16(sB + sn*GST*4 + stA0, Bg + (size_t)brow *K + k0 + ach*8);
            cp16(sB + sn*GST*4 + stA1, Bg + (size_t)brow2*K + k0 + ach*8);
        }
        CP_COMMIT();

        const unsigned aS = sA + (kt%3)*GST*4;
        const unsigned bS = sB + (kt%3)*GST*4;
#pragma unroll
        for (int kc8 = 0; kc8 < 16; kc8 += 8) {
            unsigned af[4][4];
#pragma unroll
            for (int ma=0;ma<4;ma++)
                ldsm4(af[ma], aS + afo[ma] + kc8*4);
#pragma unroll
            for (int nb=0;nb<2;nb++) {
                unsigned bq[4];
                ldsm4(bq, bS + bfo[nb] + kc8*4);
                unsigned b0[2] = {bq[0], bq[2]};
                unsigned b1[2] = {bq[1], bq[3]};
#pragma unroll
                for (int ma=0;ma<4;ma++) {
                    mma_h16(acc[ma][nb*2  ], af[ma], b0);
                    mma_h16(acc[ma][nb*2+1], af[ma], b1);
                }
            }
        }
    }

    const int r = lane >> 2, c = lane & 3;
#pragma unroll
    for (int ma=0;ma<4;ma++) {
        int m = blockIdx.y*128 + wm*64 + ma*16 + r;
#pragma unroll
        for (int na=0;na<4;na++) {
            int n = blockIdx.x*128 + wn*32 + na*8 + 2*c;
            if (n < N) {
                if (OUTF32) {
                    float* C = (float*)Cv;
                    *(float2*)&C[(size_t)m*ldc + n]     = make_float2(acc[ma][na][0], acc[ma][na][1]);
                    *(float2*)&C[(size_t)(m+8)*ldc + n] = make_float2(acc[ma][na][2], acc[ma][na][3]);
                } else {
                    __half* C = (__half*)Cv;
                    *(__half2*)&C[(size_t)m*ldc + n]     = __floats2half2_rn(acc[ma][na][0], acc[ma][na][1]);
                    *(__half2*)&C[(size_t)(m+8)*ldc + n] = __floats2half2_rn(acc[ma][na][2], acc[ma][na][3]);
                }
            }
        }
    }
}

// ---------------- V transpose: g_c2[bl][2048 + h*128+d] -> g_vt [bh][d][l] -
__global__ void __launch_bounds__(256) vtrans()
{
    __shared__ __half t[64][DHh+8];
    const int bh = blockIdx.y, b = bh >> 4, h = bh & 15;
    const int l0 = blockIdx.x * 64;
    const int tid = threadIdx.x;

    for (int i = tid; i < 64*16; i += 256) {
        int l = i >> 4, ch = i & 15;
        *(uint4*)&t[l][ch*8] =
            *(const uint4*)(g_c2 + ((size_t)(b*Ll + l0 + l))*N2 + Dd + h*DHh + ch*8);
    }
    __syncthreads();
    for (int i = tid; i < 128*8; i += 256) {
        int d = i >> 3, ch = i & 7;
        __half2 p[4];
#pragma unroll
        for (int u=0;u<4;u++) {
            int l = ch*8 + u*2;
            p[u] = __halves2half2(t[l][d], t[l+1][d]);
        }
        *(uint4*)(g_vt + (size_t)bh*DHh*Ll + (size_t)d*Ll + l0 + ch*8) = *(uint4*)p;
    }
}

// ---------------- prep: RoPE + concat + normalize + scale ------------------
__global__ void __launch_bounds__(192) prep2(const float* __restrict__ s_qk_ptr)
{
    const int bl = blockIdx.x, h = blockIdx.y;
    const int b = bl >> 11, l = bl & 2047;
    const int t = threadIdx.x;

    __shared__ float red[2][6];
    const float s_qk = *s_qk_ptr;

    float kv, qv;
    if (t < 128) {
        kv = __half2float(g_c2[(size_t)bl*N2 + h*DHh + t]);          // kc
        qv = __half2float(g_c3[(size_t)bl*N3 + h*DHh + t]);          // qc
    } else {
        int j = t - 128, jj = j & 31;
        float inv = powf(10000.0f, -(float)jj/32.0f);
        float ang = (float)l * inv;
        float csv = cosf(ang), snv = sinf(ang);
        {
            const __half* krp = g_c1 + (size_t)bl*N1 + 2*DCc;        // kr
            float v  = __half2float(krp[j]);
            float vo = __half2float(krp[(j<32 ? j+32 : j-32)]);
            float rot = (j<32) ? -vo : vo;
            kv = v*csv + rot*snv;
        }
        {
            const __half* qrp = g_c3 + (size_t)bl*N3 + Dd + h*DHRr;  // qr
            float v  = __half2float(qrp[j]);
            float vo = __half2float(qrp[(j<32 ? j+32 : j-32)]);
            float rot = (j<32) ? -vo : vo;
            qv = v*csv + rot*snv;
        }
    }

    float ks = kv*kv, qs = qv*qv;
#pragma unroll
    for (int o=16;o>0;o>>=1) {
        ks += __shfl_xor_sync(0xffffffffu, ks, o);
        qs += __shfl_xor_sync(0xffffffffu, qs, o);
    }
    const int w = t >> 5;
    if ((t & 31) == 0) { red[0][w] = ks; red[1][w] = qs; }
    __syncthreads();
    float ksum = red[0][0]+red[0][1]+red[0][2]+red[0][3]+red[0][4]+red[0][5];
    float qsum = red[1][0]+red[1][1]+red[1][2]+red[1][3]+red[1][4]+red[1][5];
    float invk = 1.0f / fmaxf(sqrtf(ksum), 1e-12f);
    float invq = s_qk / fmaxf(sqrtf(qsum), 1e-12f);

    size_t off = ((size_t)(b*NHh + h)*Ll + l)*QKD + t;
    g_k[off] = __float2half(kv*invk);
    g_q[off] = __float2half(qv*invq);
}

// ---------------- fp16 flash attention (causal, BQ=128, BK=64) -------------
#define QS 100
#define VS 36
#define KST (64*QS)
#define VST (128*VS)
__global__ void __launch_bounds__(256, 1) attn_h16()
{
    extern __shared__ unsigned smu[];
    unsigned* Qs = smu;                        // [128][100]
    const unsigned sQ = smem_u32(Qs);
    const unsigned sK = sQ + 128*QS*4;         // 2 stages [64][100]
    const unsigned sV = sK + 2*KST*4;          // 2 stages [128][36]
    const unsigned sP = sV + 2*VST*4;          // [128][36]
    unsigned* Ps = smu + (128*QS + 2*KST + 2*VST);

    const int qt = (gridDim.x - 1) - blockIdx.x;
    const int bh = blockIdx.y;
    const int q0 = qt * 128;
    const __half* Qg = g_q  + (size_t)bh*Ll*QKD + (size_t)q0*QKD;
    const __half* Kg = g_k  + (size_t)bh*Ll*QKD;
    const __half* Vg = g_vt + (size_t)bh*DHh*Ll;

    const int tid  = threadIdx.x;
    const int lane = tid & 31;
    const int warp = tid >> 5;
    const int r = lane >> 2, c = lane & 3;
    const int ln15 = lane & 15;
    const int hi16 = (lane >> 4) * 16;
    const int m0 = warp * 16;

    for (int i = tid; i < 128*24; i += 256) {
        int row = i / 24, ch = i % 24;
        *(uint4*)&Qs[row*QS + ch*4] = *(const uint4*)(Qg + (size_t)row*QKD + ch*8);
    }

    const unsigned qbase = sQ + ((m0 + ln15)*QS)*4 + hi16;
    const unsigned pbase = sP + ((m0 + ln15)*VS)*4 + hi16;

    float O[16][4];
#pragma unroll
    for (int nb=0; nb<16; nb++)
#pragma unroll
        for (int t=0; t<4; t++) O[nb][t] = 0.f;
    float m_i[2] = {-1e30f, -1e30f};
    float l_i[2] = {0.f, 0.f};

    const int nkt = 2*(qt+1);

    {
        for (int i = tid; i < 64*24; i += 256) {
            int row = i / 24, ch = i % 24;
            cp16(sK + (row*QS + ch*4)*4, Kg + (size_t)row*QKD + ch*8);
        }
        for (int i = tid; i < 128*8; i += 256) {
            int d = i >> 3, ch = i & 7;
            cp16(sV + (d*VS + ch*4)*4, Vg + (size_t)d*Ll + ch*8);
        }
        CP_COMMIT();
    }

    for (int kt = 0; kt < nkt; kt++) {
        if (kt+1 < nkt) {
            const int k0n = (kt+1)*64;
            const unsigned kS = sK + ((kt+1)&1)*KST*4;
            const unsigned vS = sV + ((kt+1)&1)*VST*4;
            for (int i = tid; i < 64*24; i += 256) {
                int row = i / 24, ch = i % 24;
                cp16(kS + (row*QS + ch*4)*4, Kg + (size_t)(k0n+row)*QKD + ch*8);
            }
            for (int i = tid; i < 128*8; i += 256) {
                int d = i >> 3, ch = i & 7;
                cp16(vS + (d*VS + ch*4)*4, Vg + (size_t)d*Ll + k0n + ch*8);
            }
        }
        CP_COMMIT();
        CP_WAIT(1);
        __syncthreads();

        const unsigned kS = sK + (kt&1)*KST*4;
        const unsigned vS = sV + (kt&1)*VST*4;
        const int k0 = kt*64;

        float S[8][4];
#pragma unroll
        for (int j=0;j<8;j++)
#pragma unroll
            for (int t=0;t<4;t++) S[j][t]=0.f;

#pragma unroll
        for (int kk = 0; kk < 12; kk++) {
            unsigned a[4];
            ldsm4(a, qbase + kk*32);
#pragma unroll
            for (int p = 0; p < 4; p++) {
                unsigned bq[4];
                ldsm4(bq, kS + ((p*16 + ln15)*QS)*4 + hi16 + kk*32);
                unsigned b0[2] = {bq[0], bq[2]};
                unsigned b1[2] = {bq[1], bq[3]};
                mma_h16(S[p*2  ], a, b0);
                mma_h16(S[p*2+1], a, b1);
            }
        }

        if (kt >= nkt - 2) {
            const int row0 = q0 + m0 + r;
            const int row1 = row0 + 8;
#pragma unroll
            for (int j = 0; j < 8; j++) {
                int col = k0 + j*8 + 2*c;
                if (col   > row0) S[j][0] = -1e30f;
                if (col+1 > row0) S[j][1] = -1e30f;
                if (col   > row1) S[j][2] = -1e30f;
                if (col+1 > row1) S[j][3] = -1e30f;
            }
        }

        float mx0 = -1e30f, mx1 = -1e30f;
#pragma unroll
        for (int j=0;j<8;j++) {
            mx0 = fmaxf(mx0, fmaxf(S[j][0], S[j][1]));
            mx1 = fmaxf(mx1, fmaxf(S[j][2], S[j][3]));
        }
        mx0 = fmaxf(mx0, __shfl_xor_sync(0xffffffffu, mx0, 1));
        mx0 = fmaxf(mx0, __shfl_xor_sync(0xffffffffu, mx0, 2));
        mx1 = fmaxf(mx1, __shfl_xor_sync(0xffffffffu, mx1, 1));
        mx1 = fmaxf(mx1, __shfl_xor_sync(0xffffffffu, mx1, 2));

        float mn0 = fmaxf(m_i[0], mx0), mn1 = fmaxf(m_i[1], mx1);
        float corr0 = __expf(m_i[0]-mn0), corr1 = __expf(m_i[1]-mn1);
        float rs0 = 0.f, rs1 = 0.f;
#pragma unroll
        for (int j=0;j<8;j++) {
            S[j][0] = __expf(S[j][0]-mn0); rs0 += S[j][0];
            S[j][1] = __expf(S[j][1]-mn0); rs0 += S[j][1];
            S[j][2] = __expf(S[j][2]-mn1); rs1 += S[j][2];
            S[j][3] = __expf(S[j][3]-mn1); rs1 += S[j][3];
        }
        rs0 += __shfl_xor_sync(0xffffffffu, rs0, 1);
        rs0 += __shfl_xor_sync(0xffffffffu, rs0, 2);
        rs1 += __shfl_xor_sync(0xffffffffu, rs1, 1);
        rs1 += __shfl_xor_sync(0xffffffffu, rs1, 2);
        l_i[0] = l_i[0]*corr0 + rs0;  m_i[0] = mn0;
        l_i[1] = l_i[1]*corr1 + rs1;  m_i[1] = mn1;

#pragma unroll
        for (int nb=0; nb<16; nb++) {
            O[nb][0]*=corr0; O[nb][1]*=corr0;
            O[nb][2]*=corr1; O[nb][3]*=corr1;
        }

#pragma unroll
        for (int j=0;j<8;j++) {
            __half2 p0 = __floats2half2_rn(S[j][0], S[j][1]);
            __half2 p1 = __floats2half2_rn(S[j][2], S[j][3]);
            Ps[(m0+r  )*VS + j*4 + c] = *(unsigned*)&p0;
            Ps[(m0+r+8)*VS + j*4 + c] = *(unsigned*)&p1;
        }
        __syncwarp();

#pragma unroll
        for (int kk = 0; kk < 4; kk++) {
            unsigned a[4];
            ldsm4(a, pbase + kk*32);
#pragma unroll
            for (int p = 0; p < 8; p++) {
                unsigned bq[4];
                ldsm4(bq, vS + ((p*16 + ln15)*VS)*4 + hi16 + kk*32);
                unsigned b0[2] = {bq[0], bq[2]};
                unsigned b1[2] = {bq[1], bq[3]};
                mma_h16(O[p*2  ], a, b0);
                mma_h16(O[p*2+1], a, b1);
            }
        }
        __syncthreads();
    }

    const int b = bh >> 4, h = bh & 15;
    const float inv0 = 1.0f / l_i[0];
    const float inv1 = 1.0f / l_i[1];
    const int l0 = q0 + m0 + r;
    __half* d0 = g_ao + ((size_t)(b*Ll + l0    ))*Dd + h*DHh;
    __half* d1 = g_ao + ((size_t)(b*Ll + l0 + 8))*Dd + h*DHh;
#pragma unroll
    for (int nb=0; nb<16; nb++) {
        *(__half2*)&d0[nb*8 + 2*c] = __floats2half2_rn(O[nb][0]*inv0, O[nb][1]*inv0);
        *(__half2*)&d1[nb*8 + 2*c] = __floats2half2_rn(O[nb][2]*inv1, O[nb][3]*inv1);
    }
}

// ---------------- launch ----------------
extern "C" void kernel_launch(void* const* d_in, const int* in_sizes, int n_in,
                              void* d_out, int out_size)
{
    const float* x     = (const float*)d_in[0];
    const float* W_DKV = (const float*)d_in[1];
    const float* W_UK  = (const float*)d_in[2];
    const float* W_UV  = (const float*)d_in[3];
    const float* W_DQ  = (const float*)d_in[4];
    const float* W_UQ  = (const float*)d_in[5];
    const float* W_QR  = (const float*)d_in[6];
    const float* W_KR  = (const float*)d_in[7];
    const float* W_O   = (const float*)d_in[8];
    const float* s_qk  = (const float*)d_in[9];
    float* out = (float*)d_out;

    __half *xh, *w1t, *w2t, *w3t, *woT, *c1, *c3, *ao;
    cudaGetSymbolAddress((void**)&xh,  g_xh);
    cudaGetSymbolAddress((void**)&w1t, g_w1t);
    cudaGetSymbolAddress((void**)&w2t, g_w2t);
    cudaGetSymbolAddress((void**)&w3t, g_w3t);
    cudaGetSymbolAddress((void**)&woT, g_woT);
    cudaGetSymbolAddress((void**)&c1,  g_c1);
    __half* c2; cudaGetSymbolAddress((void**)&c2, g_c2);
    cudaGetSymbolAddress((void**)&c3,  g_c3);
    cudaGetSymbolAddress((void**)&ao,  g_ao);

    const int gemm_smem = 6*GST*4;                                   // 61440
    cudaFuncSetAttribute(h16_gemm<false>, cudaFuncAttributeMaxDynamicSharedMemorySize, gemm_smem);
    cudaFuncSetAttribute(h16_gemm<true>,  cudaFuncAttributeMaxDynamicSharedMemorySize, gemm_smem);
    const int attn_smem = (128*QS + 2*KST + 2*VST + 128*VS) * 4;     // 157696
    cudaFuncSetAttribute(attn_h16, cudaFuncAttributeMaxDynamicSharedMemorySize, attn_smem);

    dim3 thr(256);

    // ---- pre-pass: fp16 conversions / transposes into fused buffers ----
    cvt_x<<<(Mtok*Dd/4 + 255)/256, thr>>>(x, xh, Mtok*Dd/4);
    wtrans<<<dim3(DCc/32, Dd/32),  thr>>>(W_DKV, w1t,                          Dd, DCc);
    wtrans<<<dim3(DCc/32, Dd/32),  thr>>>(W_DQ,  w1t + (size_t)DCc*Dd,         Dd, DCc);
    wtrans<<<dim3(DHRr/32, Dd/32), thr>>>(W_KR,  w1t + (size_t)2*DCc*Dd,       Dd, DHRr);
    wtrans<<<dim3(Dd/32, DCc/32),  thr>>>(W_UK,  w2t,                          DCc, Dd);
    wtrans<<<dim3(Dd/32, DCc/32),  thr>>>(W_UV,  w2t + (size_t)Dd*DCc,         DCc, Dd);
    wtrans<<<dim3(Dd/32, DCc/32),  thr>>>(W_UQ,  w3t,                          DCc, Dd);
    wtrans<<<dim3((NHh*DHRr)/32, DCc/32), thr>>>(W_QR, w3t + (size_t)Dd*DCc,   DCc, NHh*DHRr);
    wtrans<<<dim3(Dd/32, Dd/32),   thr>>>(W_O,   woT,                          Dd, Dd);

    // ---- fused projections (fp16 tensor cores) ----
    // G1: x -> [ckv | cq | kr]
    h16_gemm<false><<<dim3((N1+127)/128, Mtok/128), thr, gemm_smem>>>(xh, w1t, c1, N1, Dd, Dd, N1);
    // G2: ckv -> [kc | vfl]
    h16_gemm<false><<<dim3(N2/128, Mtok/128), thr, gemm_smem>>>(c1, w2t, c2, N2, DCc, N1, N2);
    // G3: cq -> [qc | qr]
    h16_gemm<false><<<dim3(N3/128, Mtok/128), thr, gemm_smem>>>(c1 + DCc, w3t, c3, N3, DCc, N1, N3);

    // ---- V transpose + prep ----
    vtrans<<<dim3(Ll/64, Bb*NHh), thr>>>();
    prep2<<<dim3(Mtok, NHh), 192>>>(s_qk);

    // ---- attention ----
    attn_h16<<<dim3(Ll/128, Bb*NHh), thr, attn_smem>>>();

    // ---- output projection -> d_out (fp32 out) ----
    h16_gemm<true><<<dim3(Dd/128, Mtok/128), thr, gemm_smem>>>(ao, woT, out, Dd, Dd, Dd, Dd);
}

// round 9
// speedup vs baseline: 9.0869x; 1.0192x over previous
#include <cuda_runtime.h>
#include <cuda_fp16.h>
#include <math.h>

// ---------------- problem constants ----------------
#define Bb 4
#define Ll 2048
#define Dd 2048
#define NHh 16
#define DHh 128
#define DHRr 64
#define DCc 1024
#define Mtok (Bb*Ll)            // 8192
#define QKD 192                 // DH + DHR
#define N1 (DCc + DCc + DHRr)   // 2112 : [ckv | cq | kr]
#define N2 (Dd + Dd)            // 4096 : [kc | vfl]
#define N3 (Dd + NHh*DHRr)      // 3072 : [qc | qr]

// ---------------- device scratch (static, allocation-free) ----------------
__device__ __half g_xh  [(size_t)Mtok*Dd];
__device__ __half g_w1t [(size_t)N1*Dd];
__device__ __half g_w2t [(size_t)N2*DCc];
__device__ __half g_w3t [(size_t)N3*DCc];
__device__ __half g_woT [(size_t)Dd*Dd];
__device__ __half g_c1  [(size_t)Mtok*N1];   // ckv | cq | kr
__device__ __half g_c2  [(size_t)Mtok*N2];   // kc | vfl
__device__ __half g_c3  [(size_t)Mtok*N3];   // qc | qr
__device__ __half g_q   [(size_t)Bb*NHh*Ll*QKD];
__device__ __half g_k   [(size_t)Bb*NHh*Ll*QKD];
__device__ __half g_vt  [(size_t)Bb*NHh*DHh*Ll];   // [bh][d][l]
__device__ __half g_ao  [(size_t)Mtok*Dd];

// ---------------- asm helpers ----------------
__device__ __forceinline__ void mma_h16(float* d, const unsigned* a, const unsigned* b) {
    asm volatile(
        "mma.sync.aligned.m16n8k16.row.col.f32.f16.f16.f32 "
        "{%0,%1,%2,%3}, {%4,%5,%6,%7}, {%8,%9}, {%0,%1,%2,%3};"
        : "+f"(d[0]), "+f"(d[1]), "+f"(d[2]), "+f"(d[3])
        : "r"(a[0]), "r"(a[1]), "r"(a[2]), "r"(a[3]), "r"(b[0]), "r"(b[1]));
}

__device__ __forceinline__ unsigned smem_u32(const void* p) {
    return (unsigned)__cvta_generic_to_shared(p);
}

__device__ __forceinline__ void ldsm4(unsigned* r, unsigned addr) {
    asm volatile("ldmatrix.sync.aligned.m8n8.x4.shared.b16 {%0,%1,%2,%3}, [%4];"
        : "=r"(r[0]), "=r"(r[1]), "=r"(r[2]), "=r"(r[3]) : "r"(addr));
}

__device__ __forceinline__ void cp16(unsigned dst, const void* src) {
    asm volatile("cp.async.cg.shared.global [%0], [%1], 16;" :: "r"(dst), "l"(src));
}
#define CP_COMMIT() asm volatile("cp.async.commit_group;")
#define CP_WAIT(N)  asm volatile("cp.async.wait_group %0;" :: "n"(N))

// ---------------- pre-pass: x fp32 -> fp16 ----------------
__global__ void __launch_bounds__(256) cvt_x(const float* __restrict__ x, __half* __restrict__ xh, int n4)
{
    int i = blockIdx.x*256 + threadIdx.x;
    if (i < n4) {
        float4 v = ((const float4*)x)[i];
        __half2* o = (__half2*)xh;
        o[2*i]   = __floats2half2_rn(v.x, v.y);
        o[2*i+1] = __floats2half2_rn(v.z, v.w);
    }
}

// ---------------- pre-pass: W [K][N] fp32 -> Wt [N][K] fp16 ----------------
__global__ void __launch_bounds__(256) wtrans(const float* __restrict__ W, __half* __restrict__ Wt,
                                              int K, int N)
{
    __shared__ __half t[32][33];
    const int n0 = blockIdx.x*32, k0 = blockIdx.y*32;
    const int tx = threadIdx.x & 31, ty = threadIdx.x >> 5;   // 32x8
#pragma unroll
    for (int i=0;i<4;i++)
        t[ty+i*8][tx] = __float2half(W[(size_t)(k0+ty+i*8)*N + n0+tx]);
    __syncthreads();
#pragma unroll
    for (int i=0;i<4;i++)
        Wt[(size_t)(n0+ty+i*8)*K + k0+tx] = t[tx][ty+i*8];
}

// ---------------- fp16 tensor-core GEMM: C[M][N] = A * Bt^T ----------------
// 128x128 CTA tile; K-stages of 64 halves; 3-stage cp.async ring; ldmatrix;
// 8 warps (2x4), 64x32 warp tile; 2 CTAs/SM.
#define SW 36                        // words per k64 row (32 + 4 pad)
#define GST (128*SW)                 // words per operand per stage (4608)
template<bool OUTF32>
__global__ void __launch_bounds__(256, 2)
h16_gemm(const __half* __restrict__ A, const __half* __restrict__ Bt,
         void* __restrict__ Cv, int N, int K, int lda, int ldc)
{
    extern __shared__ unsigned gsm[];
    const unsigned sA = smem_u32(gsm);            // 3 stages A
    const unsigned sB = sA + 3*GST*4;             // 3 stages B

    const int tid  = threadIdx.x;
    const int lane = tid & 31;
    const int warp = tid >> 5;
    const int wm = warp >> 2, wn = warp & 3;
    const int ln15 = lane & 15;
    const int hi16 = (lane >> 4) * 16;

    const __half* Ag = A  + (size_t)blockIdx.y * 128 * lda;
    const __half* Bg = Bt + (size_t)blockIdx.x * 128 * K;
    const int nrem = N - blockIdx.x*128;

    // fill mapping: 1024 chunks of 16B per operand per stage -> 4 per thread
    const int frow = tid >> 1;                    // 0..127 (2 half-rows/thread? no:)
    // use idx-based mapping inside the fill loops instead

    unsigned afo[4], bfo[2];
#pragma unroll
    for (int ma=0; ma<4; ma++) afo[ma] = ((wm*64 + ma*16 + ln15)*SW)*4 + hi16;
#pragma unroll
    for (int nb=0; nb<2; nb++) bfo[nb] = ((wn*32 + nb*16 + ln15)*SW)*4 + hi16;

    float acc[4][4][4];
#pragma unroll
    for (int i=0;i<4;i++)
#pragma unroll
        for (int j=0;j<4;j++)
#pragma unroll
            for (int t=0;t<4;t++) acc[i][j][t]=0.f;

    const int nk = K/64;

    // stage fill: A/B 128 rows x 64 halves, 8 chunks/row, padded stride SW
    auto fill = [&](int s, int k0) {
        const unsigned aB = sA + s*GST*4;
        const unsigned bB = sB + s*GST*4;
#pragma unroll
        for (int i = 0; i < 4; i++) {
            int idx = tid + i*256;                // 0..1023
            int row = idx >> 3, ch = idx & 7;
            cp16(aB + row*SW*4 + ch*16, Ag + (size_t)row*lda + k0 + ch*8);
        }
#pragma unroll
        for (int i = 0; i < 4; i++) {
            int idx = tid + i*256;
            int row = idx >> 3, ch = idx & 7;
            int gr = (row < nrem) ? row : (nrem-1);
            cp16(bB + row*SW*4 + ch*16, Bg + (size_t)gr*K + k0 + ch*8);
        }
    };

    fill(0, 0);  CP_COMMIT();
    fill(1, 64); CP_COMMIT();

    for (int kt=0; kt<nk; kt++) {
        CP_WAIT(1);
        __syncthreads();

        const int kn = kt+2;
        if (kn < nk) fill(kn % 3, kn*64);
        CP_COMMIT();

        const unsigned aS = sA + (kt%3)*GST*4;
        const unsigned bS = sB + (kt%3)*GST*4;
#pragma unroll
        for (int kc8 = 0; kc8 < 32; kc8 += 8) {   // four k16 chunks
            unsigned af[4][4];
#pragma unroll
            for (int ma=0;ma<4;ma++)
                ldsm4(af[ma], aS + afo[ma] + kc8*4);
#pragma unroll
            for (int nb=0;nb<2;nb++) {
                unsigned bq[4];
                ldsm4(bq, bS + bfo[nb] + kc8*4);
                unsigned b0[2] = {bq[0], bq[2]};
                unsigned b1[2] = {bq[1], bq[3]};
#pragma unroll
                for (int ma=0;ma<4;ma++) {
                    mma_h16(acc[ma][nb*2  ], af[ma], b0);
                    mma_h16(acc[ma][nb*2+1], af[ma], b1);
                }
            }
        }
    }

    const int r = lane >> 2, c = lane & 3;
#pragma unroll
    for (int ma=0;ma<4;ma++) {
        int m = blockIdx.y*128 + wm*64 + ma*16 + r;
#pragma unroll
        for (int na=0;na<4;na++) {
            int n = blockIdx.x*128 + wn*32 + na*8 + 2*c;
            if (n < N) {
                if (OUTF32) {
                    float* C = (float*)Cv;
                    *(float2*)&C[(size_t)m*ldc + n]     = make_float2(acc[ma][na][0], acc[ma][na][1]);
                    *(float2*)&C[(size_t)(m+8)*ldc + n] = make_float2(acc[ma][na][2], acc[ma][na][3]);
                } else {
                    __half* C = (__half*)Cv;
                    *(__half2*)&C[(size_t)m*ldc + n]     = __floats2half2_rn(acc[ma][na][0], acc[ma][na][1]);
                    *(__half2*)&C[(size_t)(m+8)*ldc + n] = __floats2half2_rn(acc[ma][na][2], acc[ma][na][3]);
                }
            }
        }
    }
}

// ---------------- V transpose: g_c2[bl][2048 + h*128+d] -> g_vt [bh][d][l] -
__global__ void __launch_bounds__(256) vtrans()
{
    __shared__ __half t[64][DHh+8];
    const int bh = blockIdx.y, b = bh >> 4, h = bh & 15;
    const int l0 = blockIdx.x * 64;
    const int tid = threadIdx.x;

    for (int i = tid; i < 64*16; i += 256) {
        int l = i >> 4, ch = i & 15;
        *(uint4*)&t[l][ch*8] =
            *(const uint4*)(g_c2 + ((size_t)(b*Ll + l0 + l))*N2 + Dd + h*DHh + ch*8);
    }
    __syncthreads();
    for (int i = tid; i < 128*8; i += 256) {
        int d = i >> 3, ch = i & 7;
        __half2 p[4];
#pragma unroll
        for (int u=0;u<4;u++) {
            int l = ch*8 + u*2;
            p[u] = __halves2half2(t[l][d], t[l+1][d]);
        }
        *(uint4*)(g_vt + (size_t)bh*DHh*Ll + (size_t)d*Ll + l0 + ch*8) = *(uint4*)p;
    }
}

// ---------------- prep: RoPE + concat + normalize + scale ------------------
__global__ void __launch_bounds__(192) prep2(const float* __restrict__ s_qk_ptr)
{
    const int bl = blockIdx.x, h = blockIdx.y;
    const int b = bl >> 11, l = bl & 2047;
    const int t = threadIdx.x;

    __shared__ float red[2][6];
    const float s_qk = *s_qk_ptr;

    float kv, qv;
    if (t < 128) {
        kv = __half2float(g_c2[(size_t)bl*N2 + h*DHh + t]);
        qv = __half2float(g_c3[(size_t)bl*N3 + h*DHh + t]);
    } else {
        int j = t - 128, jj = j & 31;
        float inv = powf(10000.0f, -(float)jj/32.0f);
        float ang = (float)l * inv;
        float csv = cosf(ang), snv = sinf(ang);
        {
            const __half* krp = g_c1 + (size_t)bl*N1 + 2*DCc;
            float v  = __half2float(krp[j]);
            float vo = __half2float(krp[(j<32 ? j+32 : j-32)]);
            float rot = (j<32) ? -vo : vo;
            kv = v*csv + rot*snv;
        }
        {
            const __half* qrp = g_c3 + (size_t)bl*N3 + Dd + h*DHRr;
            float v  = __half2float(qrp[j]);
            float vo = __half2float(qrp[(j<32 ? j+32 : j-32)]);
            float rot = (j<32) ? -vo : vo;
            qv = v*csv + rot*snv;
        }
    }

    float ks = kv*kv, qs = qv*qv;
#pragma unroll
    for (int o=16;o>0;o>>=1) {
        ks += __shfl_xor_sync(0xffffffffu, ks, o);
        qs += __shfl_xor_sync(0xffffffffu, qs, o);
    }
    const int w = t >> 5;
    if ((t & 31) == 0) { red[0][w] = ks; red[1][w] = qs; }
    __syncthreads();
    float ksum = red[0][0]+red[0][1]+red[0][2]+red[0][3]+red[0][4]+red[0][5];
    float qsum = red[1][0]+red[1][1]+red[1][2]+red[1][3]+red[1][4]+red[1][5];
    float invk = 1.0f / fmaxf(sqrtf(ksum), 1e-12f);
    float invq = s_qk / fmaxf(sqrtf(qsum), 1e-12f);

    size_t off = ((size_t)(b*NHh + h)*Ll + l)*QKD + t;
    g_k[off] = __float2half(kv*invk);
    g_q[off] = __float2half(qv*invq);
}

// ---------------- fp16 flash attention (causal, BQ=128, BK=64) -------------
#define QS 100
#define VS 36
#define KST (64*QS)
#define VST (128*VS)
__global__ void __launch_bounds__(256, 1) attn_h16()
{
    extern __shared__ unsigned smu[];
    unsigned* Qs = smu;
    const unsigned sQ = smem_u32(Qs);
    const unsigned sK = sQ + 128*QS*4;
    const unsigned sV = sK + 2*KST*4;
    const unsigned sP = sV + 2*VST*4;
    unsigned* Ps = smu + (128*QS + 2*KST + 2*VST);

    const int qt = (gridDim.x - 1) - blockIdx.x;
    const int bh = blockIdx.y;
    const int q0 = qt * 128;
    const __half* Qg = g_q  + (size_t)bh*Ll*QKD + (size_t)q0*QKD;
    const __half* Kg = g_k  + (size_t)bh*Ll*QKD;
    const __half* Vg = g_vt + (size_t)bh*DHh*Ll;

    const int tid  = threadIdx.x;
    const int lane = tid & 31;
    const int warp = tid >> 5;
    const int r = lane >> 2, c = lane & 3;
    const int ln15 = lane & 15;
    const int hi16 = (lane >> 4) * 16;
    const int m0 = warp * 16;

    for (int i = tid; i < 128*24; i += 256) {
        int row = i / 24, ch = i % 24;
        *(uint4*)&Qs[row*QS + ch*4] = *(const uint4*)(Qg + (size_t)row*QKD + ch*8);
    }

    const unsigned qbase = sQ + ((m0 + ln15)*QS)*4 + hi16;
    const unsigned pbase = sP + ((m0 + ln15)*VS)*4 + hi16;

    float O[16][4];
#pragma unroll
    for (int nb=0; nb<16; nb++)
#pragma unroll
        for (int t2=0; t2<4; t2++) O[nb][t2] = 0.f;
    float m_i[2] = {-1e30f, -1e30f};
    float l_i[2] = {0.f, 0.f};

    const int nkt = 2*(qt+1);

    {
        for (int i = tid; i < 64*24; i += 256) {
            int row = i / 24, ch = i % 24;
            cp16(sK + (row*QS + ch*4)*4, Kg + (size_t)row*QKD + ch*8);
        }
        for (int i = tid; i < 128*8; i += 256) {
            int d = i >> 3, ch = i & 7;
            cp16(sV + (d*VS + ch*4)*4, Vg + (size_t)d*Ll + ch*8);
        }
        CP_COMMIT();
    }

    for (int kt = 0; kt < nkt; kt++) {
        if (kt+1 < nkt) {
            const int k0n = (kt+1)*64;
            const unsigned kS = sK + ((kt+1)&1)*KST*4;
            const unsigned vS = sV + ((kt+1)&1)*VST*4;
            for (int i = tid; i < 64*24; i += 256) {
                int row = i / 24, ch = i % 24;
                cp16(kS + (row*QS + ch*4)*4, Kg + (size_t)(k0n+row)*QKD + ch*8);
            }
            for (int i = tid; i < 128*8; i += 256) {
                int d = i >> 3, ch = i & 7;
                cp16(vS + (d*VS + ch*4)*4, Vg + (size_t)d*Ll + k0n + ch*8);
            }
        }
        CP_COMMIT();
        CP_WAIT(1);
        __syncthreads();

        const unsigned kS = sK + (kt&1)*KST*4;
        const unsigned vS = sV + (kt&1)*VST*4;
        const int k0 = kt*64;

        float S[8][4];
#pragma unroll
        for (int j=0;j<8;j++)
#pragma unroll
            for (int t2=0;t2<4;t2++) S[j][t2]=0.f;

#pragma unroll
        for (int kk = 0; kk < 12; kk++) {
            unsigned a[4];
            ldsm4(a, qbase + kk*32);
#pragma unroll
            for (int p = 0; p < 4; p++) {
                unsigned bq[4];
                ldsm4(bq, kS + ((p*16 + ln15)*QS)*4 + hi16 + kk*32);
                unsigned b0[2] = {bq[0], bq[2]};
                unsigned b1[2] = {bq[1], bq[3]};
                mma_h16(S[p*2  ], a, b0);
                mma_h16(S[p*2+1], a, b1);
            }
        }

        if (kt >= nkt - 2) {
            const int row0 = q0 + m0 + r;
            const int row1 = row0 + 8;
#pragma unroll
            for (int j = 0; j < 8; j++) {
                int col = k0 + j*8 + 2*c;
                if (col   > row0) S[j][0] = -1e30f;
                if (col+1 > row0) S[j][1] = -1e30f;
                if (col   > row1) S[j][2] = -1e30f;
                if (col+1 > row1) S[j][3] = -1e30f;
            }
        }

        float mx0 = -1e30f, mx1 = -1e30f;
#pragma unroll
        for (int j=0;j<8;j++) {
            mx0 = fmaxf(mx0, fmaxf(S[j][0], S[j][1]));
            mx1 = fmaxf(mx1, fmaxf(S[j][2], S[j][3]));
        }
        mx0 = fmaxf(mx0, __shfl_xor_sync(0xffffffffu, mx0, 1));
        mx0 = fmaxf(mx0, __shfl_xor_sync(0xffffffffu, mx0, 2));
        mx1 = fmaxf(mx1, __shfl_xor_sync(0xffffffffu, mx1, 1));
        mx1 = fmaxf(mx1, __shfl_xor_sync(0xffffffffu, mx1, 2));

        float mn0 = fmaxf(m_i[0], mx0), mn1 = fmaxf(m_i[1], mx1);
        float corr0 = __expf(m_i[0]-mn0), corr1 = __expf(m_i[1]-mn1);
        float rs0 = 0.f, rs1 = 0.f;
#pragma unroll
        for (int j=0;j<8;j++) {
            S[j][0] = __expf(S[j][0]-mn0); rs0 += S[j][0];
            S[j][1] = __expf(S[j][1]-mn0); rs0 += S[j][1];
            S[j][2] = __expf(S[j][2]-mn1); rs1 += S[j][2];
            S[j][3] = __expf(S[j][3]-mn1); rs1 += S[j][3];
        }
        rs0 += __shfl_xor_sync(0xffffffffu, rs0, 1);
        rs0 += __shfl_xor_sync(0xffffffffu, rs0, 2);
        rs1 += __shfl_xor_sync(0xffffffffu, rs1, 1);
        rs1 += __shfl_xor_sync(0xffffffffu, rs1, 2);
        l_i[0] = l_i[0]*corr0 + rs0;  m_i[0] = mn0;
        l_i[1] = l_i[1]*corr1 + rs1;  m_i[1] = mn1;

#pragma unroll
        for (int nb=0; nb<16; nb++) {
            O[nb][0]*=corr0; O[nb][1]*=corr0;
            O[nb][2]*=corr1; O[nb][3]*=corr1;
        }

#pragma unroll
        for (int j=0;j<8;j++) {
            __half2 p0 = __floats2half2_rn(S[j][0], S[j][1]);
            __half2 p1 = __floats2half2_rn(S[j][2], S[j][3]);
            Ps[(m0+r  )*VS + j*4 + c] = *(unsigned*)&p0;
            Ps[(m0+r+8)*VS + j*4 + c] = *(unsigned*)&p1;
        }
        __syncwarp();

#pragma unroll
        for (int kk = 0; kk < 4; kk++) {
            unsigned a[4];
            ldsm4(a, pbase + kk*32);
#pragma unroll
            for (int p = 0; p < 8; p++) {
                unsigned bq[4];
                ldsm4(bq, vS + ((p*16 + ln15)*VS)*4 + hi16 + kk*32);
                unsigned b0[2] = {bq[0], bq[2]};
                unsigned b1[2] = {bq[1], bq[3]};
                mma_h16(O[p*2  ], a, b0);
                mma_h16(O[p*2+1], a, b1);
            }
        }
        __syncthreads();
    }

    const int b = bh >> 4, h = bh & 15;
    const float inv0 = 1.0f / l_i[0];
    const float inv1 = 1.0f / l_i[1];
    const int l0 = q0 + m0 + r;
    __half* d0 = g_ao + ((size_t)(b*Ll + l0    ))*Dd + h*DHh;
    __half* d1 = g_ao + ((size_t)(b*Ll + l0 + 8))*Dd + h*DHh;
#pragma unroll
    for (int nb=0; nb<16; nb++) {
        *(__half2*)&d0[nb*8 + 2*c] = __floats2half2_rn(O[nb][0]*inv0, O[nb][1]*inv0);
        *(__half2*)&d1[nb*8 + 2*c] = __floats2half2_rn(O[nb][2]*inv1, O[nb][3]*inv1);
    }
}

// ---------------- launch ----------------
extern "C" void kernel_launch(void* const* d_in, const int* in_sizes, int n_in,
                              void* d_out, int out_size)
{
    const float* x     = (const float*)d_in[0];
    const float* W_DKV = (const float*)d_in[1];
    const float* W_UK  = (const float*)d_in[2];
    const float* W_UV  = (const float*)d_in[3];
    const float* W_DQ  = (const float*)d_in[4];
    const float* W_UQ  = (const float*)d_in[5];
    const float* W_QR  = (const float*)d_in[6];
    const float* W_KR  = (const float*)d_in[7];
    const float* W_O   = (const float*)d_in[8];
    const float* s_qk  = (const float*)d_in[9];
    float* out = (float*)d_out;

    __half *xh, *w1t, *w2t, *w3t, *woT, *c1, *c2, *c3, *ao;
    cudaGetSymbolAddress((void**)&xh,  g_xh);
    cudaGetSymbolAddress((void**)&w1t, g_w1t);
    cudaGetSymbolAddress((void**)&w2t, g_w2t);
    cudaGetSymbolAddress((void**)&w3t, g_w3t);
    cudaGetSymbolAddress((void**)&woT, g_woT);
    cudaGetSymbolAddress((void**)&c1,  g_c1);
    cudaGetSymbolAddress((void**)&c2,  g_c2);
    cudaGetSymbolAddress((void**)&c3,  g_c3);
    cudaGetSymbolAddress((void**)&ao,  g_ao);

    const int gemm_smem = 6*GST*4;                                   // 110592
    cudaFuncSetAttribute(h16_gemm<false>, cudaFuncAttributeMaxDynamicSharedMemorySize, gemm_smem);
    cudaFuncSetAttribute(h16_gemm<true>,  cudaFuncAttributeMaxDynamicSharedMemorySize, gemm_smem);
    const int attn_smem = (128*QS + 2*KST + 2*VST + 128*VS) * 4;     // 157696
    cudaFuncSetAttribute(attn_h16, cudaFuncAttributeMaxDynamicSharedMemorySize, attn_smem);

    dim3 thr(256);

    // ---- pre-pass: fp16 conversions / transposes into fused buffers ----
    cvt_x<<<(Mtok*Dd/4 + 255)/256, thr>>>(x, xh, Mtok*Dd/4);
    wtrans<<<dim3(DCc/32, Dd/32),  thr>>>(W_DKV, w1t,                          Dd, DCc);
    wtrans<<<dim3(DCc/32, Dd/32),  thr>>>(W_DQ,  w1t + (size_t)DCc*Dd,         Dd, DCc);
    wtrans<<<dim3(DHRr/32, Dd/32), thr>>>(W_KR,  w1t + (size_t)2*DCc*Dd,       Dd, DHRr);
    wtrans<<<dim3(Dd/32, DCc/32),  thr>>>(W_UK,  w2t,                          DCc, Dd);
    wtrans<<<dim3(Dd/32, DCc/32),  thr>>>(W_UV,  w2t + (size_t)Dd*DCc,         DCc, Dd);
    wtrans<<<dim3(Dd/32, DCc/32),  thr>>>(W_UQ,  w3t,                          DCc, Dd);
    wtrans<<<dim3((NHh*DHRr)/32, DCc/32), thr>>>(W_QR, w3t + (size_t)Dd*DCc,   DCc, NHh*DHRr);
    wtrans<<<dim3(Dd/32, Dd/32),   thr>>>(W_O,   woT,                          Dd, Dd);

    // ---- fused projections (fp16 tensor cores) ----
    h16_gemm<false><<<dim3((N1+127)/128, Mtok/128), thr, gemm_smem>>>(xh, w1t, c1, N1, Dd, Dd, N1);
    h16_gemm<false><<<dim3(N2/128, Mtok/128), thr, gemm_smem>>>(c1, w2t, c2, N2, DCc, N1, N2);
    h16_gemm<false><<<dim3(N3/128, Mtok/128), thr, gemm_smem>>>(c1 + DCc, w3t, c3, N3, DCc, N1, N3);

    // ---- V transpose + prep ----
    vtrans<<<dim3(Ll/64, Bb*NHh), thr>>>();
    prep2<<<dim3(Mtok, NHh), 192>>>(s_qk);

    // ---- attention ----
    attn_h16<<<dim3(Ll/128, Bb*NHh), thr, attn_smem>>>();

    // ---- output projection -> d_out (fp32 out) ----
    h16_gemm<true><<<dim3(Dd/128, Mtok/128), thr, gemm_smem>>>(ao, woT, out, Dd, Dd, Dd, Dd);
}

// round 10
// speedup vs baseline: 9.1055x; 1.0020x over previous
#include <cuda_runtime.h>
#include <cuda_fp16.h>
#include <math.h>

// ---------------- problem constants ----------------
#define Bb 4
#define Ll 2048
#define Dd 2048
#define NHh 16
#define DHh 128
#define DHRr 64
#define DCc 1024
#define Mtok (Bb*Ll)            // 8192
#define QKD 192                 // DH + DHR
#define N1 (DCc + DCc + DHRr)   // 2112 : [ckv | cq | kr]
#define N2 (Dd + Dd)            // 4096 : [kc | vfl]
#define N3 (Dd + NHh*DHRr)      // 3072 : [qc | qr]

// ---------------- device scratch (static, allocation-free) ----------------
__device__ __half g_xh  [(size_t)Mtok*Dd];
__device__ __half g_w1t [(size_t)N1*Dd];
__device__ __half g_w2t [(size_t)N2*DCc];
__device__ __half g_w3t [(size_t)N3*DCc];
__device__ __half g_woT [(size_t)Dd*Dd];
__device__ __half g_c1  [(size_t)Mtok*N1];   // ckv | cq | kr
__device__ __half g_c2  [(size_t)Mtok*N2];   // kc | vfl
__device__ __half g_c3  [(size_t)Mtok*N3];   // qc | qr
__device__ __half g_q   [(size_t)Bb*NHh*Ll*QKD];
__device__ __half g_k   [(size_t)Bb*NHh*Ll*QKD];
__device__ __half g_vt  [(size_t)Bb*NHh*DHh*Ll];   // [bh][d][l]
__device__ __half g_ao  [(size_t)Mtok*Dd];
__device__ float  g_cs  [Ll*32];
__device__ float  g_sn  [Ll*32];

// ---------------- asm helpers ----------------
__device__ __forceinline__ void mma_h16(float* d, const unsigned* a, const unsigned* b) {
    asm volatile(
        "mma.sync.aligned.m16n8k16.row.col.f32.f16.f16.f32 "
        "{%0,%1,%2,%3}, {%4,%5,%6,%7}, {%8,%9}, {%0,%1,%2,%3};"
        : "+f"(d[0]), "+f"(d[1]), "+f"(d[2]), "+f"(d[3])
        : "r"(a[0]), "r"(a[1]), "r"(a[2]), "r"(a[3]), "r"(b[0]), "r"(b[1]));
}

__device__ __forceinline__ unsigned smem_u32(const void* p) {
    return (unsigned)__cvta_generic_to_shared(p);
}

__device__ __forceinline__ void ldsm4(unsigned* r, unsigned addr) {
    asm volatile("ldmatrix.sync.aligned.m8n8.x4.shared.b16 {%0,%1,%2,%3}, [%4];"
        : "=r"(r[0]), "=r"(r[1]), "=r"(r[2]), "=r"(r[3]) : "r"(addr));
}

__device__ __forceinline__ void cp16(unsigned dst, const void* src) {
    asm volatile("cp.async.cg.shared.global [%0], [%1], 16;" :: "r"(dst), "l"(src));
}
#define CP_COMMIT() asm volatile("cp.async.commit_group;")
#define CP_WAIT(N)  asm volatile("cp.async.wait_group %0;" :: "n"(N))

// ---------------- pre-pass: rope tables ----------------
__global__ void rope_tab()
{
    const int l  = blockIdx.x;
    const int jj = threadIdx.x;        // 0..31
    float inv = powf(10000.0f, -(float)jj/32.0f);
    float ang = (float)l * inv;
    g_cs[l*32 + jj] = cosf(ang);
    g_sn[l*32 + jj] = sinf(ang);
}

// ---------------- pre-pass: x fp32 -> fp16 ----------------
__global__ void __launch_bounds__(256) cvt_x(const float* __restrict__ x, __half* __restrict__ xh, int n4)
{
    int i = blockIdx.x*256 + threadIdx.x;
    if (i < n4) {
        float4 v = ((const float4*)x)[i];
        __half2* o = (__half2*)xh;
        o[2*i]   = __floats2half2_rn(v.x, v.y);
        o[2*i+1] = __floats2half2_rn(v.z, v.w);
    }
}

// ---------------- pre-pass: W [K][N] fp32 -> Wt [N][K] fp16 ----------------
__global__ void __launch_bounds__(256) wtrans(const float* __restrict__ W, __half* __restrict__ Wt,
                                              int K, int N)
{
    __shared__ __half t[32][33];
    const int n0 = blockIdx.x*32, k0 = blockIdx.y*32;
    const int tx = threadIdx.x & 31, ty = threadIdx.x >> 5;   // 32x8
#pragma unroll
    for (int i=0;i<4;i++)
        t[ty+i*8][tx] = __float2half(W[(size_t)(k0+ty+i*8)*N + n0+tx]);
    __syncthreads();
#pragma unroll
    for (int i=0;i<4;i++)
        Wt[(size_t)(n0+ty+i*8)*K + k0+tx] = t[tx][ty+i*8];
}

// ---------------- fp16 tensor-core GEMM: C[M][N] = A * Bt^T ----------------
// 128x128 CTA tile; K-stages of 64 halves; 3-stage cp.async ring; ldmatrix;
// 8 warps (2x4), 64x32 warp tile; 2 CTAs/SM.
#define SW 36                        // words per k64 row (32 + 4 pad)
#define GST (128*SW)                 // words per operand per stage (4608)
template<bool OUTF32>
__global__ void __launch_bounds__(256, 2)
h16_gemm(const __half* __restrict__ A, const __half* __restrict__ Bt,
         void* __restrict__ Cv, int N, int K, int lda, int ldc)
{
    extern __shared__ unsigned gsm[];
    const unsigned sA = smem_u32(gsm);            // 3 stages A
    const unsigned sB = sA + 3*GST*4;             // 3 stages B

    const int tid  = threadIdx.x;
    const int lane = tid & 31;
    const int warp = tid >> 5;
    const int wm = warp >> 2, wn = warp & 3;
    const int ln15 = lane & 15;
    const int hi16 = (lane >> 4) * 16;

    const __half* Ag = A  + (size_t)blockIdx.y * 128 * lda;
    const __half* Bg = Bt + (size_t)blockIdx.x * 128 * K;
    const int nrem = N - blockIdx.x*128;

    unsigned afo[4], bfo[2];
#pragma unroll
    for (int ma=0; ma<4; ma++) afo[ma] = ((wm*64 + ma*16 + ln15)*SW)*4 + hi16;
#pragma unroll
    for (int nb=0; nb<2; nb++) bfo[nb] = ((wn*32 + nb*16 + ln15)*SW)*4 + hi16;

    float acc[4][4][4];
#pragma unroll
    for (int i=0;i<4;i++)
#pragma unroll
        for (int j=0;j<4;j++)
#pragma unroll
            for (int t=0;t<4;t++) acc[i][j][t]=0.f;

    const int nk = K/64;

    auto fill = [&](int s, int k0) {
        const unsigned aB = sA + s*GST*4;
        const unsigned bB = sB + s*GST*4;
#pragma unroll
        for (int i = 0; i < 4; i++) {
            int idx = tid + i*256;                // 0..1023
            int row = idx >> 3, ch = idx & 7;
            cp16(aB + row*SW*4 + ch*16, Ag + (size_t)row*lda + k0 + ch*8);
        }
#pragma unroll
        for (int i = 0; i < 4; i++) {
            int idx = tid + i*256;
            int row = idx >> 3, ch = idx & 7;
            int gr = (row < nrem) ? row : (nrem-1);
            cp16(bB + row*SW*4 + ch*16, Bg + (size_t)gr*K + k0 + ch*8);
        }
    };

    fill(0, 0);  CP_COMMIT();
    fill(1, 64); CP_COMMIT();

    for (int kt=0; kt<nk; kt++) {
        CP_WAIT(1);
        __syncthreads();

        const int kn = kt+2;
        if (kn < nk) fill(kn % 3, kn*64);
        CP_COMMIT();

        const unsigned aS = sA + (kt%3)*GST*4;
        const unsigned bS = sB + (kt%3)*GST*4;
#pragma unroll
        for (int kc8 = 0; kc8 < 32; kc8 += 8) {   // four k16 chunks
            unsigned af[4][4];
#pragma unroll
            for (int ma=0;ma<4;ma++)
                ldsm4(af[ma], aS + afo[ma] + kc8*4);
#pragma unroll
            for (int nb=0;nb<2;nb++) {
                unsigned bq[4];
                ldsm4(bq, bS + bfo[nb] + kc8*4);
                unsigned b0[2] = {bq[0], bq[2]};
                unsigned b1[2] = {bq[1], bq[3]};
#pragma unroll
                for (int ma=0;ma<4;ma++) {
                    mma_h16(acc[ma][nb*2  ], af[ma], b0);
                    mma_h16(acc[ma][nb*2+1], af[ma], b1);
                }
            }
        }
    }

    const int r = lane >> 2, c = lane & 3;
#pragma unroll
    for (int ma=0;ma<4;ma++) {
        int m = blockIdx.y*128 + wm*64 + ma*16 + r;
#pragma unroll
        for (int na=0;na<4;na++) {
            int n = blockIdx.x*128 + wn*32 + na*8 + 2*c;
            if (n < N) {
                if (OUTF32) {
                    float* C = (float*)Cv;
                    *(float2*)&C[(size_t)m*ldc + n]     = make_float2(acc[ma][na][0], acc[ma][na][1]);
                    *(float2*)&C[(size_t)(m+8)*ldc + n] = make_float2(acc[ma][na][2], acc[ma][na][3]);
                } else {
                    __half* C = (__half*)Cv;
                    *(__half2*)&C[(size_t)m*ldc + n]     = __floats2half2_rn(acc[ma][na][0], acc[ma][na][1]);
                    *(__half2*)&C[(size_t)(m+8)*ldc + n] = __floats2half2_rn(acc[ma][na][2], acc[ma][na][3]);
                }
            }
        }
    }
}

// ---------------- V transpose: g_c2[bl][2048 + h*128+d] -> g_vt [bh][d][l] -
__global__ void __launch_bounds__(256) vtrans()
{
    __shared__ __half t[64][DHh+8];
    const int bh = blockIdx.y, b = bh >> 4, h = bh & 15;
    const int l0 = blockIdx.x * 64;
    const int tid = threadIdx.x;

    for (int i = tid; i < 64*16; i += 256) {
        int l = i >> 4, ch = i & 15;
        *(uint4*)&t[l][ch*8] =
            *(const uint4*)(g_c2 + ((size_t)(b*Ll + l0 + l))*N2 + Dd + h*DHh + ch*8);
    }
    __syncthreads();
    for (int i = tid; i < 128*8; i += 256) {
        int d = i >> 3, ch = i & 7;
        __half2 p[4];
#pragma unroll
        for (int u=0;u<4;u++) {
            int l = ch*8 + u*2;
            p[u] = __halves2half2(t[l][d], t[l+1][d]);
        }
        *(uint4*)(g_vt + (size_t)bh*DHh*Ll + (size_t)d*Ll + l0 + ch*8) = *(uint4*)p;
    }
}

// ---------------- prep: RoPE + concat + normalize + scale ------------------
__global__ void __launch_bounds__(192) prep2(const float* __restrict__ s_qk_ptr)
{
    const int bl = blockIdx.x, h = blockIdx.y;
    const int b = bl >> 11, l = bl & 2047;
    const int t = threadIdx.x;

    __shared__ float red[2][6];
    const float s_qk = *s_qk_ptr;

    float kv, qv;
    if (t < 128) {
        kv = __half2float(g_c2[(size_t)bl*N2 + h*DHh + t]);
        qv = __half2float(g_c3[(size_t)bl*N3 + h*DHh + t]);
    } else {
        int j = t - 128, jj = j & 31;
        float csv = g_cs[l*32 + jj];
        float snv = g_sn[l*32 + jj];
        {
            const __half* krp = g_c1 + (size_t)bl*N1 + 2*DCc;
            float v  = __half2float(krp[j]);
            float vo = __half2float(krp[(j<32 ? j+32 : j-32)]);
            float rot = (j<32) ? -vo : vo;
            kv = v*csv + rot*snv;
        }
        {
            const __half* qrp = g_c3 + (size_t)bl*N3 + Dd + h*DHRr;
            float v  = __half2float(qrp[j]);
            float vo = __half2float(qrp[(j<32 ? j+32 : j-32)]);
            float rot = (j<32) ? -vo : vo;
            qv = v*csv + rot*snv;
        }
    }

    float ks = kv*kv, qs = qv*qv;
#pragma unroll
    for (int o=16;o>0;o>>=1) {
        ks += __shfl_xor_sync(0xffffffffu, ks, o);
        qs += __shfl_xor_sync(0xffffffffu, qs, o);
    }
    const int w = t >> 5;
    if ((t & 31) == 0) { red[0][w] = ks; red[1][w] = qs; }
    __syncthreads();
    float ksum = red[0][0]+red[0][1]+red[0][2]+red[0][3]+red[0][4]+red[0][5];
    float qsum = red[1][0]+red[1][1]+red[1][2]+red[1][3]+red[1][4]+red[1][5];
    float invk = 1.0f / fmaxf(sqrtf(ksum), 1e-12f);
    float invq = s_qk / fmaxf(sqrtf(qsum), 1e-12f);

    size_t off = ((size_t)(b*NHh + h)*Ll + l)*QKD + t;
    g_k[off] = __float2half(kv*invk);
    g_q[off] = __float2half(qv*invq);
}

// ---------------- fp16 flash attention (causal, BQ=128, BK=64) -------------
// Q fragments held in registers (loaded once via ldmatrix in prologue).
#define QS 100
#define VS 36
#define KST (64*QS)
#define VST (128*VS)
__global__ void __launch_bounds__(256, 1) attn_h16()
{
    extern __shared__ unsigned smu[];
    unsigned* Qs = smu;
    const unsigned sQ = smem_u32(Qs);
    const unsigned sK = sQ + 128*QS*4;
    const unsigned sV = sK + 2*KST*4;
    const unsigned sP = sV + 2*VST*4;
    unsigned* Ps = smu + (128*QS + 2*KST + 2*VST);

    const int qt = (gridDim.x - 1) - blockIdx.x;
    const int bh = blockIdx.y;
    const int q0 = qt * 128;
    const __half* Qg = g_q  + (size_t)bh*Ll*QKD + (size_t)q0*QKD;
    const __half* Kg = g_k  + (size_t)bh*Ll*QKD;
    const __half* Vg = g_vt + (size_t)bh*DHh*Ll;

    const int tid  = threadIdx.x;
    const int lane = tid & 31;
    const int warp = tid >> 5;
    const int r = lane >> 2, c = lane & 3;
    const int ln15 = lane & 15;
    const int hi16 = (lane >> 4) * 16;
    const int m0 = warp * 16;

    for (int i = tid; i < 128*24; i += 256) {
        int row = i / 24, ch = i % 24;
        *(uint4*)&Qs[row*QS + ch*4] = *(const uint4*)(Qg + (size_t)row*QKD + ch*8);
    }

    // prologue K/V stage 0 (issue before the Q barrier to overlap)
    {
        for (int i = tid; i < 64*24; i += 256) {
            int row = i / 24, ch = i % 24;
            cp16(sK + (row*QS + ch*4)*4, Kg + (size_t)row*QKD + ch*8);
        }
        for (int i = tid; i < 128*8; i += 256) {
            int d = i >> 3, ch = i & 7;
            cp16(sV + (d*VS + ch*4)*4, Vg + (size_t)d*Ll + ch*8);
        }
        CP_COMMIT();
    }

    // Q fragments -> registers (once)
    __syncthreads();
    const unsigned qbase = sQ + ((m0 + ln15)*QS)*4 + hi16;
    unsigned qf[12][4];
#pragma unroll
    for (int kk = 0; kk < 12; kk++)
        ldsm4(qf[kk], qbase + kk*32);

    const unsigned pbase = sP + ((m0 + ln15)*VS)*4 + hi16;

    float O[16][4];
#pragma unroll
    for (int nb=0; nb<16; nb++)
#pragma unroll
        for (int t2=0; t2<4; t2++) O[nb][t2] = 0.f;
    float m_i[2] = {-1e30f, -1e30f};
    float l_i[2] = {0.f, 0.f};

    const int nkt = 2*(qt+1);

    for (int kt = 0; kt < nkt; kt++) {
        if (kt+1 < nkt) {
            const int k0n = (kt+1)*64;
            const unsigned kS = sK + ((kt+1)&1)*KST*4;
            const unsigned vS = sV + ((kt+1)&1)*VST*4;
            for (int i = tid; i < 64*24; i += 256) {
                int row = i / 24, ch = i % 24;
                cp16(kS + (row*QS + ch*4)*4, Kg + (size_t)(k0n+row)*QKD + ch*8);
            }
            for (int i = tid; i < 128*8; i += 256) {
                int d = i >> 3, ch = i & 7;
                cp16(vS + (d*VS + ch*4)*4, Vg + (size_t)d*Ll + k0n + ch*8);
            }
        }
        CP_COMMIT();
        CP_WAIT(1);
        __syncthreads();

        const unsigned kS = sK + (kt&1)*KST*4;
        const unsigned vS = sV + (kt&1)*VST*4;
        const int k0 = kt*64;

        float S[8][4];
#pragma unroll
        for (int j=0;j<8;j++)
#pragma unroll
            for (int t2=0;t2<4;t2++) S[j][t2]=0.f;

#pragma unroll
        for (int kk = 0; kk < 12; kk++) {
#pragma unroll
            for (int p = 0; p < 4; p++) {
                unsigned bq[4];
                ldsm4(bq, kS + ((p*16 + ln15)*QS)*4 + hi16 + kk*32);
                unsigned b0[2] = {bq[0], bq[2]};
                unsigned b1[2] = {bq[1], bq[3]};
                mma_h16(S[p*2  ], qf[kk], b0);
                mma_h16(S[p*2+1], qf[kk], b1);
            }
        }

        if (kt >= nkt - 2) {
            const int row0 = q0 + m0 + r;
            const int row1 = row0 + 8;
#pragma unroll
            for (int j = 0; j < 8; j++) {
                int col = k0 + j*8 + 2*c;
                if (col   > row0) S[j][0] = -1e30f;
                if (col+1 > row0) S[j][1] = -1e30f;
                if (col   > row1) S[j][2] = -1e30f;
                if (col+1 > row1) S[j][3] = -1e30f;
            }
        }

        float mx0 = -1e30f, mx1 = -1e30f;
#pragma unroll
        for (int j=0;j<8;j++) {
            mx0 = fmaxf(mx0, fmaxf(S[j][0], S[j][1]));
            mx1 = fmaxf(mx1, fmaxf(S[j][2], S[j][3]));
        }
        mx0 = fmaxf(mx0, __shfl_xor_sync(0xffffffffu, mx0, 1));
        mx0 = fmaxf(mx0, __shfl_xor_sync(0xffffffffu, mx0, 2));
        mx1 = fmaxf(mx1, __shfl_xor_sync(0xffffffffu, mx1, 1));
        mx1 = fmaxf(mx1, __shfl_xor_sync(0xffffffffu, mx1, 2));

        float mn0 = fmaxf(m_i[0], mx0), mn1 = fmaxf(m_i[1], mx1);
        float corr0 = __expf(m_i[0]-mn0), corr1 = __expf(m_i[1]-mn1);
        float rs0 = 0.f, rs1 = 0.f;
#pragma unroll
        for (int j=0;j<8;j++) {
            S[j][0] = __expf(S[j][0]-mn0); rs0 += S[j][0];
            S[j][1] = __expf(S[j][1]-mn0); rs0 += S[j][1];
            S[j][2] = __expf(S[j][2]-mn1); rs1 += S[j][2];
            S[j][3] = __expf(S[j][3]-mn1); rs1 += S[j][3];
        }
        rs0 += __shfl_xor_sync(0xffffffffu, rs0, 1);
        rs0 += __shfl_xor_sync(0xffffffffu, rs0, 2);
        rs1 += __shfl_xor_sync(0xffffffffu, rs1, 1);
        rs1 += __shfl_xor_sync(0xffffffffu, rs1, 2);
        l_i[0] = l_i[0]*corr0 + rs0;  m_i[0] = mn0;
        l_i[1] = l_i[1]*corr1 + rs1;  m_i[1] = mn1;

#pragma unroll
        for (int nb=0; nb<16; nb++) {
            O[nb][0]*=corr0; O[nb][1]*=corr0;
            O[nb][2]*=corr1; O[nb][3]*=corr1;
        }

#pragma unroll
        for (int j=0;j<8;j++) {
            __half2 p0 = __floats2half2_rn(S[j][0], S[j][1]);
            __half2 p1 = __floats2half2_rn(S[j][2], S[j][3]);
            Ps[(m0+r  )*VS + j*4 + c] = *(unsigned*)&p0;
            Ps[(m0+r+8)*VS + j*4 + c] = *(unsigned*)&p1;
        }
        __syncwarp();

#pragma unroll
        for (int kk = 0; kk < 4; kk++) {
            unsigned a[4];
            ldsm4(a, pbase + kk*32);
#pragma unroll
            for (int p = 0; p < 8; p++) {
                unsigned bq[4];
                ldsm4(bq, vS + ((p*16 + ln15)*VS)*4 + hi16 + kk*32);
                unsigned b0[2] = {bq[0], bq[2]};
                unsigned b1[2] = {bq[1], bq[3]};
                mma_h16(O[p*2  ], a, b0);
                mma_h16(O[p*2+1], a, b1);
            }
        }
        __syncthreads();
    }

    const int b = bh >> 4, h = bh & 15;
    const float inv0 = 1.0f / l_i[0];
    const float inv1 = 1.0f / l_i[1];
    const int l0 = q0 + m0 + r;
    __half* d0 = g_ao + ((size_t)(b*Ll + l0    ))*Dd + h*DHh;
    __half* d1 = g_ao + ((size_t)(b*Ll + l0 + 8))*Dd + h*DHh;
#pragma unroll
    for (int nb=0; nb<16; nb++) {
        *(__half2*)&d0[nb*8 + 2*c] = __floats2half2_rn(O[nb][0]*inv0, O[nb][1]*inv0);
        *(__half2*)&d1[nb*8 + 2*c] = __floats2half2_rn(O[nb][2]*inv1, O[nb][3]*inv1);
    }
}

// ---------------- launch ----------------
extern "C" void kernel_launch(void* const* d_in, const int* in_sizes, int n_in,
                              void* d_out, int out_size)
{
    const float* x     = (const float*)d_in[0];
    const float* W_DKV = (const float*)d_in[1];
    const float* W_UK  = (const float*)d_in[2];
    const float* W_UV  = (const float*)d_in[3];
    const float* W_DQ  = (const float*)d_in[4];
    const float* W_UQ  = (const float*)d_in[5];
    const float* W_QR  = (const float*)d_in[6];
    const float* W_KR  = (const float*)d_in[7];
    const float* W_O   = (const float*)d_in[8];
    const float* s_qk  = (const float*)d_in[9];
    float* out = (float*)d_out;

    __half *xh, *w1t, *w2t, *w3t, *woT, *c1, *c2, *c3, *ao;
    cudaGetSymbolAddress((void**)&xh,  g_xh);
    cudaGetSymbolAddress((void**)&w1t, g_w1t);
    cudaGetSymbolAddress((void**)&w2t, g_w2t);
    cudaGetSymbolAddress((void**)&w3t, g_w3t);
    cudaGetSymbolAddress((void**)&woT, g_woT);
    cudaGetSymbolAddress((void**)&c1,  g_c1);
    cudaGetSymbolAddress((void**)&c2,  g_c2);
    cudaGetSymbolAddress((void**)&c3,  g_c3);
    cudaGetSymbolAddress((void**)&ao,  g_ao);

    const int gemm_smem = 6*GST*4;                                   // 110592
    cudaFuncSetAttribute(h16_gemm<false>, cudaFuncAttributeMaxDynamicSharedMemorySize, gemm_smem);
    cudaFuncSetAttribute(h16_gemm<true>,  cudaFuncAttributeMaxDynamicSharedMemorySize, gemm_smem);
    const int attn_smem = (128*QS + 2*KST + 2*VST + 128*VS) * 4;     // 157696
    cudaFuncSetAttribute(attn_h16, cudaFuncAttributeMaxDynamicSharedMemorySize, attn_smem);

    dim3 thr(256);

    // ---- pre-pass: rope tables + fp16 conversions / transposes ----
    rope_tab<<<Ll, 32>>>();
    cvt_x<<<(Mtok*Dd/4 + 255)/256, thr>>>(x, xh, Mtok*Dd/4);
    wtrans<<<dim3(DCc/32, Dd/32),  thr>>>(W_DKV, w1t,                          Dd, DCc);
    wtrans<<<dim3(DCc/32, Dd/32),  thr>>>(W_DQ,  w1t + (size_t)DCc*Dd,         Dd, DCc);
    wtrans<<<dim3(DHRr/32, Dd/32), thr>>>(W_KR,  w1t + (size_t)2*DCc*Dd,       Dd, DHRr);
    wtrans<<<dim3(Dd/32, DCc/32),  thr>>>(W_UK,  w2t,                          DCc, Dd);
    wtrans<<<dim3(Dd/32, DCc/32),  thr>>>(W_UV,  w2t + (size_t)Dd*DCc,         DCc, Dd);
    wtrans<<<dim3(Dd/32, DCc/32),  thr>>>(W_UQ,  w3t,                          DCc, Dd);
    wtrans<<<dim3((NHh*DHRr)/32, DCc/32), thr>>>(W_QR, w3t + (size_t)Dd*DCc,   DCc, NHh*DHRr);
    wtrans<<<dim3(Dd/32, Dd/32),   thr>>>(W_O,   woT,                          Dd, Dd);

    // ---- fused projections (fp16 tensor cores) ----
    h16_gemm<false><<<dim3((N1+127)/128, Mtok/128), thr, gemm_smem>>>(xh, w1t, c1, N1, Dd, Dd, N1);
    h16_gemm<false><<<dim3(N2/128, Mtok/128), thr, gemm_smem>>>(c1, w2t, c2, N2, DCc, N1, N2);
    h16_gemm<false><<<dim3(N3/128, Mtok/128), thr, gemm_smem>>>(c1 + DCc, w3t, c3, N3, DCc, N1, N3);

    // ---- V transpose + prep ----
    vtrans<<<dim3(Ll/64, Bb*NHh), thr>>>();
    prep2<<<dim3(Mtok, NHh), 192>>>(s_qk);

    // ---- attention ----
    attn_h16<<<dim3(Ll/128, Bb*NHh), thr, attn_smem>>>();

    // ---- output projection -> d_out (fp32 out) ----
    h16_gemm<true><<<dim3(Dd/128, Mtok/128), thr, gemm_smem>>>(ao, woT, out, Dd, Dd, Dd, Dd);
}